// round 6
// baseline (speedup 1.0000x reference)
#include <cuda_runtime.h>
#include <cuda_bf16.h>
#include <math_constants.h>
#include <cstdint>

// Problem constants
#define EMB   1024
#define HEADS 16
#define HD    64
#define BATCH 2
#define SEQ   2048
#define M_TOT (BATCH * SEQ)
#define K2TOT (EMB / 2)        // 512 packed k-pair rows
#define BH    (BATCH * HEADS)  // 32

// ---------------------------------------------------------------------------
// Device scratch (allocation-free rule)
// ---------------------------------------------------------------------------
__device__ __align__(16) unsigned g_Xh[K2TOT * M_TOT];       // X split, k-major [k2][m]
__device__ __align__(16) unsigned g_Xl[K2TOT * M_TOT];
__device__ __align__(16) unsigned g_Wsh[4][K2TOT * EMB];     // W split, [k2][n]
__device__ __align__(16) unsigned g_Wsl[4][K2TOT * EMB];
__device__ __align__(16) unsigned g_Qh[(size_t)BH * SEQ * 32]; // [bh][n][d2]
__device__ __align__(16) unsigned g_Ql[(size_t)BH * SEQ * 32];
__device__ __align__(16) unsigned g_Kh[(size_t)BH * SEQ * 32];
__device__ __align__(16) unsigned g_Kl[(size_t)BH * SEQ * 32];
__device__ __align__(16) float    g_V [(size_t)BH * SEQ * HD]; // fp32 head-major
__device__ __align__(16) unsigned g_Vth[(size_t)BH * HD * (SEQ / 2)]; // [bh][d][n2]
__device__ __align__(16) unsigned g_Vtl[(size_t)BH * HD * (SEQ / 2)];
__device__ __align__(16) float    g_ctx[(size_t)M_TOT * EMB];
__device__ __align__(16) unsigned g_Ch[K2TOT * M_TOT];       // ctx split, k-major
__device__ __align__(16) unsigned g_Cl[K2TOT * M_TOT];

// ---------------------------------------------------------------------------
// Helpers
// ---------------------------------------------------------------------------
__device__ __forceinline__ void splitf(float v, unsigned short& h, unsigned short& l)
{
    __nv_bfloat16 hb = __float2bfloat16(v);
    float rv = v - __bfloat162float(hb);
    __nv_bfloat16 lb = __float2bfloat16(rv);
    h = ((__nv_bfloat16_raw)hb).x;
    l = ((__nv_bfloat16_raw)lb).x;
}

__device__ __forceinline__ void split2(float v0, float v1,
                                       unsigned& hp, unsigned& lp)
{
    unsigned short h0, l0, h1, l1;
    splitf(v0, h0, l0);
    splitf(v1, h1, l1);
    hp = (unsigned)h0 | ((unsigned)h1 << 16);
    lp = (unsigned)l0 | ((unsigned)l1 << 16);
}

__device__ __forceinline__ void mma_bf16(float* d,
                                         unsigned a0, unsigned a1,
                                         unsigned a2, unsigned a3,
                                         unsigned b0, unsigned b1)
{
    asm volatile(
        "mma.sync.aligned.m16n8k16.row.col.f32.bf16.bf16.f32 "
        "{%0,%1,%2,%3}, {%4,%5,%6,%7}, {%8,%9}, {%0,%1,%2,%3};\n"
        : "+f"(d[0]), "+f"(d[1]), "+f"(d[2]), "+f"(d[3])
        : "r"(a0), "r"(a1), "r"(a2), "r"(a3), "r"(b0), "r"(b1));
}

__device__ __forceinline__ unsigned smem_u32addr(const void* p)
{
    return (unsigned)__cvta_generic_to_shared(p);
}
__device__ __forceinline__ void cp_async16(unsigned dst, const void* src)
{
    asm volatile("cp.async.cg.shared.global [%0], [%1], 16;\n" :: "r"(dst), "l"(src));
}
__device__ __forceinline__ void cp_commit()
{
    asm volatile("cp.async.commit_group;\n");
}
template <int N>
__device__ __forceinline__ void cp_wait()
{
    asm volatile("cp.async.wait_group %0;\n" :: "n"(N));
}

// ---------------------------------------------------------------------------
// Prologue split kernels
// ---------------------------------------------------------------------------
// fp32 [M][1024] -> u32 packs [512][M] (k-major). grid (M/256, 512), block 256.
__global__ void split_kmajor(const float* __restrict__ in,
                             unsigned* __restrict__ outh,
                             unsigned* __restrict__ outl, int M)
{
    const int m  = blockIdx.x * 256 + threadIdx.x;
    const int k2 = blockIdx.y;
    float2 v = *(const float2*)(in + (size_t)m * EMB + 2 * k2);
    unsigned hp, lp;
    split2(v.x, v.y, hp, lp);
    outh[(size_t)k2 * M + m] = hp;
    outl[(size_t)k2 * M + m] = lp;
}

// W fp32 [1024][1024] -> u32 packs [512][1024]. grid (4, 512), block 256.
__global__ void split_w(const float* __restrict__ W,
                        unsigned* __restrict__ outh,
                        unsigned* __restrict__ outl)
{
    const int n  = blockIdx.x * 256 + threadIdx.x;
    const int k2 = blockIdx.y;
    float a = W[(size_t)(2 * k2) * EMB + n];
    float b = W[(size_t)(2 * k2 + 1) * EMB + n];
    unsigned hp, lp;
    split2(a, b, hp, lp);
    outh[(size_t)k2 * EMB + n] = hp;
    outl[(size_t)k2 * EMB + n] = lp;
}

// V fp32 [bh][n][d] -> transposed split [bh][d][n2] (key-pair packs).
// grid (SEQ/64, BH), block 256.
__global__ void split_v_t(const float* __restrict__ V,
                          unsigned* __restrict__ outh,
                          unsigned* __restrict__ outl)
{
    __shared__ float tile[64][65];
    const int tid  = threadIdx.x;
    const int bh   = blockIdx.y;
    const int nblk = blockIdx.x * 64;
    const float* src = V + (size_t)bh * SEQ * HD + (size_t)nblk * HD;
#pragma unroll
    for (int u = 0; u < 16; ++u) {
        int id = tid + 256 * u;          // 4096 elems
        int n = id >> 6, d = id & 63;
        tile[n][d] = src[n * HD + d];
    }
    __syncthreads();
    unsigned* oh = outh + (size_t)bh * HD * (SEQ / 2) + (nblk >> 1);
    unsigned* ol = outl + (size_t)bh * HD * (SEQ / 2) + (nblk >> 1);
#pragma unroll
    for (int u = 0; u < 8; ++u) {
        int id = tid + 256 * u;          // 2048 jobs
        int d = id >> 5, n2 = id & 31;
        unsigned hp, lp;
        split2(tile[2 * n2][d], tile[2 * n2 + 1][d], hp, lp);
        oh[(size_t)d * (SEQ / 2) + n2] = hp;
        ol[(size_t)d * (SEQ / 2) + n2] = lp;
    }
}

// ---------------------------------------------------------------------------
// Projection GEMM: pre-split inputs, cp.async staging.
// MODE 0: split-packed head-major output (Q/K), scale applied after bias.
// MODE 1: fp32 head-major (V).  MODE 2: fp32 row-major (final out).
// ---------------------------------------------------------------------------
#define KLD 132

template <int MODE>
__global__ __launch_bounds__(256, 2)
void proj_mma_kernel(const unsigned* __restrict__ Aht,  // [512][4096]
                     const unsigned* __restrict__ Alt,
                     const unsigned* __restrict__ Bh,   // [512][1024]
                     const unsigned* __restrict__ Bl,
                     const float* __restrict__ bias,
                     void* __restrict__ out_a,
                     void* __restrict__ out_b,
                     float oscale)
{
    __shared__ __align__(16) unsigned Ah2[16 * KLD];
    __shared__ __align__(16) unsigned Al2[16 * KLD];
    __shared__ __align__(16) unsigned Bh2[16 * KLD];
    __shared__ __align__(16) unsigned Bl2[16 * KLD];

    const int tid  = threadIdx.x;
    const int m0   = blockIdx.y * 128;
    const int n0   = blockIdx.x * 128;
    const int lane = tid & 31;
    const int wid  = tid >> 5;
    const int wm   = wid & 1;
    const int wn   = wid >> 1;
    const int g    = lane >> 2;
    const int t    = lane & 3;

    float acc[4][4][4];
#pragma unroll
    for (int i = 0; i < 4; ++i)
#pragma unroll
        for (int j = 0; j < 4; ++j)
#pragma unroll
            for (int r = 0; r < 4; ++r) acc[i][j][r] = 0.f;

    for (int k0 = 0; k0 < EMB; k0 += 32) {
        __syncthreads();
        const int kb2 = k0 >> 1;
        // A tiles (h then l): 1024 16B chunks
#pragma unroll
        for (int u = 0; u < 4; ++u) {
            int id = tid + 256 * u;
            const unsigned* src = (id < 512) ? Aht : Alt;
            unsigned* dst = (id < 512) ? Ah2 : Al2;
            int rem = id & 511;
            int k2r = rem >> 5, ch = (rem & 31) * 4;
            cp_async16(smem_u32addr(dst + k2r * KLD + ch),
                       src + (size_t)(kb2 + k2r) * M_TOT + m0 + ch);
        }
        // B tiles
#pragma unroll
        for (int u = 0; u < 4; ++u) {
            int id = tid + 256 * u;
            const unsigned* src = (id < 512) ? Bh : Bl;
            unsigned* dst = (id < 512) ? Bh2 : Bl2;
            int rem = id & 511;
            int k2r = rem >> 5, ch = (rem & 31) * 4;
            cp_async16(smem_u32addr(dst + k2r * KLD + ch),
                       src + (size_t)(kb2 + k2r) * EMB + n0 + ch);
        }
        cp_commit();
        cp_wait<0>();
        __syncthreads();

#pragma unroll
        for (int ks = 0; ks < 2; ++ks) {
            const int kb = ks * 8 + t;
            unsigned bh0[4], bh1[4], bl0[4], bl1[4];
#pragma unroll
            for (int nt = 0; nt < 4; ++nt) {
                int cc = wn * 32 + nt * 8 + g;
                bh0[nt] = Bh2[kb * KLD + cc];
                bh1[nt] = Bh2[(kb + 4) * KLD + cc];
                bl0[nt] = Bl2[kb * KLD + cc];
                bl1[nt] = Bl2[(kb + 4) * KLD + cc];
            }
#pragma unroll
            for (int mt = 0; mt < 4; ++mt) {
                int mr = wm * 64 + mt * 16 + g;
                unsigned a0h = Ah2[kb * KLD + mr];
                unsigned a1h = Ah2[kb * KLD + mr + 8];
                unsigned a2h = Ah2[(kb + 4) * KLD + mr];
                unsigned a3h = Ah2[(kb + 4) * KLD + mr + 8];
                unsigned a0l = Al2[kb * KLD + mr];
                unsigned a1l = Al2[kb * KLD + mr + 8];
                unsigned a2l = Al2[(kb + 4) * KLD + mr];
                unsigned a3l = Al2[(kb + 4) * KLD + mr + 8];
#pragma unroll
                for (int nt = 0; nt < 4; ++nt) {
                    mma_bf16(acc[mt][nt], a0h, a1h, a2h, a3h, bh0[nt], bh1[nt]);
                    mma_bf16(acc[mt][nt], a0h, a1h, a2h, a3h, bl0[nt], bl1[nt]);
                    mma_bf16(acc[mt][nt], a0l, a1l, a2l, a3l, bh0[nt], bh1[nt]);
                }
            }
        }
    }

    // ---- Epilogue ----
#pragma unroll
    for (int mt = 0; mt < 4; ++mt) {
#pragma unroll
        for (int nt = 0; nt < 4; ++nt) {
            const int row0 = m0 + wm * 64 + mt * 16 + g;
            const int col  = n0 + wn * 32 + nt * 8 + t * 2;
            const float b0v = __ldg(&bias[col]);
            const float b1v = __ldg(&bias[col + 1]);
#pragma unroll
            for (int half = 0; half < 2; ++half) {
                const int row = row0 + half * 8;
                float vx = (acc[mt][nt][half * 2 + 0] + b0v) * oscale;
                float vy = (acc[mt][nt][half * 2 + 1] + b1v) * oscale;
                if (MODE == 0) {
                    unsigned* outh = (unsigned*)out_a;
                    unsigned* outl = (unsigned*)out_b;
                    const int b  = row >> 11;
                    const int n  = row & (SEQ - 1);
                    const int h  = col >> 6;
                    const int d2 = (col & (HD - 1)) >> 1;
                    unsigned hp, lp;
                    split2(vx, vy, hp, lp);
                    size_t idx = ((size_t)(b * HEADS + h) * SEQ + n) * 32 + d2;
                    outh[idx] = hp;
                    outl[idx] = lp;
                } else if (MODE == 1) {
                    float* out = (float*)out_a;
                    const int b  = row >> 11;
                    const int n  = row & (SEQ - 1);
                    const int h  = col >> 6;
                    const int dd = col & (HD - 1);
                    float2 v; v.x = vx; v.y = vy;
                    *(float2*)(out + ((size_t)(b * HEADS + h) * SEQ + n) * HD + dd) = v;
                } else {
                    float* out = (float*)out_a;
                    float2 v; v.x = vx; v.y = vy;
                    *(float2*)(out + (size_t)row * EMB + col) = v;
                }
            }
        }
    }
}

// ---------------------------------------------------------------------------
// Flash attention: pre-split inputs, Q frags from GMEM, cp.async double-buffered
// K/V tiles (64 keys each). Warp = 16 q-rows. Only P is split in-loop.
// smem per buffer: kh/kl [key][d2] stride 36; vh/vl [d][k2] stride 36.
// ---------------------------------------------------------------------------
#define KVS 2304   // 64*36 u32 per array

__global__ __launch_bounds__(256)
void attn_mma_kernel(const unsigned* __restrict__ Qh, const unsigned* __restrict__ Ql,
                     const unsigned* __restrict__ Kh, const unsigned* __restrict__ Kl,
                     const unsigned* __restrict__ Vh, const unsigned* __restrict__ Vl,
                     float* __restrict__ ctx)
{
    extern __shared__ __align__(16) unsigned dynsm[];

    const int tid  = threadIdx.x;
    const int w    = tid >> 5;
    const int lane = tid & 31;
    const int g    = lane >> 2;
    const int t    = lane & 3;
    const int bh   = blockIdx.y;
    const int q0   = blockIdx.x * 128;

    const unsigned* Qhb = Qh + (size_t)bh * SEQ * 32;
    const unsigned* Qlb = Ql + (size_t)bh * SEQ * 32;
    const unsigned* Khb = Kh + (size_t)bh * SEQ * 32;
    const unsigned* Klb = Kl + (size_t)bh * SEQ * 32;
    const unsigned* Vhb = Vh + (size_t)bh * HD * (SEQ / 2);
    const unsigned* Vlb = Vl + (size_t)bh * HD * (SEQ / 2);

    // ---- Q fragments straight from GMEM (scale pre-folded by proj) ----
    unsigned qh[4][4], ql[4][4];
    const int r1 = q0 + w * 16 + g;
    const int r2 = r1 + 8;
#pragma unroll
    for (int ks = 0; ks < 4; ++ks) {
        int c0 = ks * 8 + t;
        qh[ks][0] = Qhb[(size_t)r1 * 32 + c0];
        qh[ks][1] = Qhb[(size_t)r2 * 32 + c0];
        qh[ks][2] = Qhb[(size_t)r1 * 32 + c0 + 4];
        qh[ks][3] = Qhb[(size_t)r2 * 32 + c0 + 4];
        ql[ks][0] = Qlb[(size_t)r1 * 32 + c0];
        ql[ks][1] = Qlb[(size_t)r2 * 32 + c0];
        ql[ks][2] = Qlb[(size_t)r1 * 32 + c0 + 4];
        ql[ks][3] = Qlb[(size_t)r2 * 32 + c0 + 4];
    }

    // ---- staging helper ----
    auto stage = [&](int buf, int kt) {
        unsigned* base = dynsm + buf * 4 * KVS;
#pragma unroll
        for (int u = 0; u < 4; ++u) {
            int id = tid + 256 * u;        // K jobs: 1024 chunks
            const unsigned* src = (id < 512) ? Khb : Klb;
            unsigned* dst = base + ((id < 512) ? 0 : KVS);
            int rem = id & 511;
            int key = rem >> 3, ch = (rem & 7) * 4;
            cp_async16(smem_u32addr(dst + key * 36 + ch),
                       src + (size_t)(kt + key) * 32 + ch);
        }
#pragma unroll
        for (int u = 0; u < 4; ++u) {
            int id = tid + 256 * u;        // V jobs: 1024 chunks
            const unsigned* src = (id < 512) ? Vhb : Vlb;
            unsigned* dst = base + 2 * KVS + ((id < 512) ? 0 : KVS);
            int rem = id & 511;
            int d = rem >> 3, ch = (rem & 7) * 4;
            cp_async16(smem_u32addr(dst + d * 36 + ch),
                       src + (size_t)d * (SEQ / 2) + (kt >> 1) + ch);
        }
        cp_commit();
    };

    float oacc[8][4];
#pragma unroll
    for (int j = 0; j < 8; ++j)
#pragma unroll
        for (int r = 0; r < 4; ++r) oacc[j][r] = 0.f;
    float m1 = -1e30f, m2 = -1e30f, l1s = 0.f, l2s = 0.f;

    stage(0, 0);

    const int NT = SEQ / 64;   // 32 tiles
    for (int it = 0; it < NT; ++it) {
        if (it + 1 < NT) {
            stage((it + 1) & 1, (it + 1) * 64);
            cp_wait<1>();
        } else {
            cp_wait<0>();
        }
        __syncthreads();

        const unsigned* kh = dynsm + (it & 1) * 4 * KVS;
        const unsigned* kl = kh + KVS;
        const unsigned* vh = kh + 2 * KVS;
        const unsigned* vl = kh + 3 * KVS;

        // ---- S-GEMM ----
        float sacc[8][4];
#pragma unroll
        for (int j = 0; j < 8; ++j)
#pragma unroll
            for (int r = 0; r < 4; ++r) sacc[j][r] = 0.f;

#pragma unroll
        for (int ks = 0; ks < 4; ++ks) {
#pragma unroll
            for (int j = 0; j < 8; ++j) {
                int ka = (8 * j + g) * 36 + ks * 8 + t;
                unsigned bh0 = kh[ka], bh1 = kh[ka + 4];
                unsigned bl0 = kl[ka], bl1 = kl[ka + 4];
                mma_bf16(sacc[j], qh[ks][0], qh[ks][1], qh[ks][2], qh[ks][3], bh0, bh1);
                mma_bf16(sacc[j], qh[ks][0], qh[ks][1], qh[ks][2], qh[ks][3], bl0, bl1);
                mma_bf16(sacc[j], ql[ks][0], ql[ks][1], ql[ks][2], ql[ks][3], bh0, bh1);
            }
        }

        // ---- Online softmax (rows g, g+8) ----
        float cm1 = -1e30f, cm2 = -1e30f;
#pragma unroll
        for (int j = 0; j < 8; ++j) {
            cm1 = fmaxf(cm1, fmaxf(sacc[j][0], sacc[j][1]));
            cm2 = fmaxf(cm2, fmaxf(sacc[j][2], sacc[j][3]));
        }
        cm1 = fmaxf(cm1, __shfl_xor_sync(0xffffffffu, cm1, 1));
        cm1 = fmaxf(cm1, __shfl_xor_sync(0xffffffffu, cm1, 2));
        cm2 = fmaxf(cm2, __shfl_xor_sync(0xffffffffu, cm2, 1));
        cm2 = fmaxf(cm2, __shfl_xor_sync(0xffffffffu, cm2, 2));
        const float mn1 = fmaxf(m1, cm1);
        const float mn2 = fmaxf(m2, cm2);
        const float f1 = __expf(m1 - mn1);
        const float f2 = __expf(m2 - mn2);
        m1 = mn1; m2 = mn2;

        float sp1 = 0.f, sp2 = 0.f;
#pragma unroll
        for (int j = 0; j < 8; ++j) {
            sacc[j][0] = __expf(sacc[j][0] - mn1);
            sacc[j][1] = __expf(sacc[j][1] - mn1);
            sacc[j][2] = __expf(sacc[j][2] - mn2);
            sacc[j][3] = __expf(sacc[j][3] - mn2);
            sp1 += sacc[j][0] + sacc[j][1];
            sp2 += sacc[j][2] + sacc[j][3];
        }
        sp1 += __shfl_xor_sync(0xffffffffu, sp1, 1);
        sp1 += __shfl_xor_sync(0xffffffffu, sp1, 2);
        sp2 += __shfl_xor_sync(0xffffffffu, sp2, 1);
        sp2 += __shfl_xor_sync(0xffffffffu, sp2, 2);
        l1s = l1s * f1 + sp1;
        l2s = l2s * f2 + sp2;

#pragma unroll
        for (int j = 0; j < 8; ++j) {
            oacc[j][0] *= f1; oacc[j][1] *= f1;
            oacc[j][2] *= f2; oacc[j][3] *= f2;
        }

        // ---- PV-GEMM ----
#pragma unroll
        for (int s = 0; s < 4; ++s) {
            unsigned a0h, a0l, a1h, a1l, a2h, a2l, a3h, a3l;
            split2(sacc[2 * s][0],     sacc[2 * s][1],     a0h, a0l);
            split2(sacc[2 * s][2],     sacc[2 * s][3],     a1h, a1l);
            split2(sacc[2 * s + 1][0], sacc[2 * s + 1][1], a2h, a2l);
            split2(sacc[2 * s + 1][2], sacc[2 * s + 1][3], a3h, a3l);
#pragma unroll
            for (int j = 0; j < 8; ++j) {
                int va = (8 * j + g) * 36 + 8 * s + t;
                unsigned vh0 = vh[va], vh1 = vh[va + 4];
                unsigned vl0 = vl[va], vl1 = vl[va + 4];
                mma_bf16(oacc[j], a0h, a1h, a2h, a3h, vh0, vh1);
                mma_bf16(oacc[j], a0h, a1h, a2h, a3h, vl0, vl1);
                mma_bf16(oacc[j], a0l, a1l, a2l, a3l, vh0, vh1);
            }
        }
        __syncthreads();
    }

    // ---- Epilogue: normalize + write ctx [b*SEQ+n][h*HD+d] ----
    const float inv1 = 1.f / l1s;
    const float inv2 = 1.f / l2s;
    const int b = bh >> 4;
    const int h = bh & 15;
#pragma unroll
    for (int j = 0; j < 8; ++j) {
        const int col = h * HD + 8 * j + 2 * t;
        float2 v1w, v2w;
        v1w.x = oacc[j][0] * inv1; v1w.y = oacc[j][1] * inv1;
        v2w.x = oacc[j][2] * inv2; v2w.y = oacc[j][3] * inv2;
        *(float2*)(ctx + (size_t)(b * SEQ + r1) * EMB + col) = v1w;
        *(float2*)(ctx + (size_t)(b * SEQ + r2) * EMB + col) = v2w;
    }
}

// ---------------------------------------------------------------------------
// Launch
// ---------------------------------------------------------------------------
extern "C" void kernel_launch(void* const* d_in, const int* in_sizes, int n_in,
                              void* d_out, int out_size)
{
    const float* x  = (const float*)d_in[0];
    const float* Wq = (const float*)d_in[1];
    const float* bq = (const float*)d_in[2];
    const float* Wk = (const float*)d_in[3];
    const float* bk = (const float*)d_in[4];
    const float* Wv = (const float*)d_in[5];
    const float* bv = (const float*)d_in[6];
    const float* Wo = (const float*)d_in[7];
    const float* bo = (const float*)d_in[8];
    float* out = (float*)d_out;

    unsigned *Xh, *Xl, *Wsh, *Wsl, *Qh, *Ql, *Kh, *Kl, *Vth, *Vtl, *Ch, *Cl;
    float *Vp, *Cp;
    cudaGetSymbolAddress((void**)&Xh,  g_Xh);
    cudaGetSymbolAddress((void**)&Xl,  g_Xl);
    cudaGetSymbolAddress((void**)&Wsh, g_Wsh);
    cudaGetSymbolAddress((void**)&Wsl, g_Wsl);
    cudaGetSymbolAddress((void**)&Qh,  g_Qh);
    cudaGetSymbolAddress((void**)&Ql,  g_Ql);
    cudaGetSymbolAddress((void**)&Kh,  g_Kh);
    cudaGetSymbolAddress((void**)&Kl,  g_Kl);
    cudaGetSymbolAddress((void**)&Vth, g_Vth);
    cudaGetSymbolAddress((void**)&Vtl, g_Vtl);
    cudaGetSymbolAddress((void**)&Vp,  g_V);
    cudaGetSymbolAddress((void**)&Cp,  g_ctx);
    cudaGetSymbolAddress((void**)&Ch,  g_Ch);
    cudaGetSymbolAddress((void**)&Cl,  g_Cl);

    const int attn_smem = 2 * 4 * KVS * 4;   // 73728 bytes
    static int configured = 0;
    if (!configured) {
        cudaFuncSetAttribute(attn_mma_kernel,
                             cudaFuncAttributeMaxDynamicSharedMemorySize,
                             attn_smem);
        configured = 1;
    }

    const size_t WSZ = (size_t)K2TOT * EMB;

    // Prologue splits
    split_kmajor<<<dim3(M_TOT / 256, K2TOT), 256>>>(x, Xh, Xl, M_TOT);
    split_w<<<dim3(EMB / 256, K2TOT), 256>>>(Wq, Wsh + 0 * WSZ, Wsl + 0 * WSZ);
    split_w<<<dim3(EMB / 256, K2TOT), 256>>>(Wk, Wsh + 1 * WSZ, Wsl + 1 * WSZ);
    split_w<<<dim3(EMB / 256, K2TOT), 256>>>(Wv, Wsh + 2 * WSZ, Wsl + 2 * WSZ);
    split_w<<<dim3(EMB / 256, K2TOT), 256>>>(Wo, Wsh + 3 * WSZ, Wsl + 3 * WSZ);

    dim3 pgrid(EMB / 128, M_TOT / 128);
    proj_mma_kernel<0><<<pgrid, 256>>>(Xh, Xl, Wsh + 0 * WSZ, Wsl + 0 * WSZ,
                                       bq, Qh, Ql, 0.03125f);
    proj_mma_kernel<0><<<pgrid, 256>>>(Xh, Xl, Wsh + 1 * WSZ, Wsl + 1 * WSZ,
                                       bk, Kh, Kl, 1.0f);
    proj_mma_kernel<1><<<pgrid, 256>>>(Xh, Xl, Wsh + 2 * WSZ, Wsl + 2 * WSZ,
                                       bv, Vp, nullptr, 1.0f);
    split_v_t<<<dim3(SEQ / 64, BH), 256>>>(Vp, Vth, Vtl);

    dim3 agrid(SEQ / 128, BH);
    attn_mma_kernel<<<agrid, 256, attn_smem>>>(Qh, Ql, Kh, Kl, Vth, Vtl, Cp);

    split_kmajor<<<dim3(M_TOT / 256, K2TOT), 256>>>(Cp, Ch, Cl, M_TOT);
    proj_mma_kernel<2><<<pgrid, 256>>>(Ch, Cl, Wsh + 3 * WSZ, Wsl + 3 * WSZ,
                                       bo, out, nullptr, 1.0f);
}

// round 7
// speedup vs baseline: 1.5447x; 1.5447x over previous
#include <cuda_runtime.h>
#include <cuda_bf16.h>
#include <math_constants.h>
#include <cstdint>

// Problem constants
#define EMB   1024
#define HEADS 16
#define HD    64
#define BATCH 2
#define SEQ   2048
#define M_TOT (BATCH * SEQ)
#define BH    (BATCH * HEADS)

// Scratch (allocation-free rule)
__device__ __align__(16) unsigned g_Qh[(size_t)BH * SEQ * 32]; // [bh][n][d2] split packs
__device__ __align__(16) unsigned g_Ql[(size_t)BH * SEQ * 32];
__device__ __align__(16) unsigned g_Kh[(size_t)BH * SEQ * 32];
__device__ __align__(16) unsigned g_Kl[(size_t)BH * SEQ * 32];
__device__ __align__(16) float    g_V [(size_t)BH * SEQ * HD]; // fp32 head-major
__device__ __align__(16) unsigned g_Vth[(size_t)BH * HD * (SEQ / 2)]; // [bh][d][n2]
__device__ __align__(16) unsigned g_Vtl[(size_t)BH * HD * (SEQ / 2)];
__device__ __align__(16) float    g_ctx[(size_t)M_TOT * EMB];

// ---------------------------------------------------------------------------
// Helpers
// ---------------------------------------------------------------------------
__device__ __forceinline__ void splitf(float v, unsigned short& h, unsigned short& l)
{
    __nv_bfloat16 hb = __float2bfloat16(v);
    float rv = v - __bfloat162float(hb);
    __nv_bfloat16 lb = __float2bfloat16(rv);
    h = ((__nv_bfloat16_raw)hb).x;
    l = ((__nv_bfloat16_raw)lb).x;
}

__device__ __forceinline__ void split2(float v0, float v1,
                                       unsigned& hp, unsigned& lp)
{
    unsigned short h0, l0, h1, l1;
    splitf(v0, h0, l0);
    splitf(v1, h1, l1);
    hp = (unsigned)h0 | ((unsigned)h1 << 16);
    lp = (unsigned)l0 | ((unsigned)l1 << 16);
}

__device__ __forceinline__ void mma_bf16(float* d,
                                         unsigned a0, unsigned a1,
                                         unsigned a2, unsigned a3,
                                         unsigned b0, unsigned b1)
{
    asm volatile(
        "mma.sync.aligned.m16n8k16.row.col.f32.bf16.bf16.f32 "
        "{%0,%1,%2,%3}, {%4,%5,%6,%7}, {%8,%9}, {%0,%1,%2,%3};\n"
        : "+f"(d[0]), "+f"(d[1]), "+f"(d[2]), "+f"(d[3])
        : "r"(a0), "r"(a1), "r"(a2), "r"(a3), "r"(b0), "r"(b1));
}

__device__ __forceinline__ unsigned smem_u32addr(const void* p)
{
    return (unsigned)__cvta_generic_to_shared(p);
}
__device__ __forceinline__ void cp_async16(unsigned dst, const void* src)
{
    asm volatile("cp.async.cg.shared.global [%0], [%1], 16;\n" :: "r"(dst), "l"(src));
}
__device__ __forceinline__ void cp_commit()
{
    asm volatile("cp.async.commit_group;\n");
}
template <int N>
__device__ __forceinline__ void cp_wait()
{
    asm volatile("cp.async.wait_group %0;\n" :: "n"(N));
}

// ---------------------------------------------------------------------------
// V fp32 [bh][n][d] -> transposed split [bh][d][n2]. grid (SEQ/64, BH), 256 thr.
// ---------------------------------------------------------------------------
__global__ void split_v_t(const float* __restrict__ V,
                          unsigned* __restrict__ outh,
                          unsigned* __restrict__ outl)
{
    __shared__ float tile[64][65];
    const int tid  = threadIdx.x;
    const int bh   = blockIdx.y;
    const int nblk = blockIdx.x * 64;
    const float* src = V + (size_t)bh * SEQ * HD + (size_t)nblk * HD;
#pragma unroll
    for (int u = 0; u < 16; ++u) {
        int id = tid + 256 * u;
        int n = id >> 6, d = id & 63;
        tile[n][d] = src[n * HD + d];
    }
    __syncthreads();
    unsigned* oh = outh + (size_t)bh * HD * (SEQ / 2) + (nblk >> 1);
    unsigned* ol = outl + (size_t)bh * HD * (SEQ / 2) + (nblk >> 1);
#pragma unroll
    for (int u = 0; u < 8; ++u) {
        int id = tid + 256 * u;
        int d = id >> 5, n2 = id & 31;
        unsigned hp, lp;
        split2(tile[2 * n2][d], tile[2 * n2 + 1][d], hp, lp);
        oh[(size_t)d * (SEQ / 2) + n2] = hp;
        ol[(size_t)d * (SEQ / 2) + n2] = lp;
    }
}

// ---------------------------------------------------------------------------
// Projection GEMM (R5-proven structure: fp32 inputs, in-kernel split staging).
// MODE 0: split-packed head-major out (Q/K), scale folded after bias.
// MODE 1: fp32 head-major (V).  MODE 2: fp32 row-major (final out).
// ---------------------------------------------------------------------------
#define KLD 132

template <int MODE>
__global__ __launch_bounds__(256, 2)
void proj_mma_kernel(const float* __restrict__ X,
                     const float* __restrict__ W,
                     const float* __restrict__ bias,
                     void* __restrict__ out_a,
                     void* __restrict__ out_b,
                     float oscale)
{
    __shared__ __align__(16) unsigned Ah2[16 * KLD];
    __shared__ __align__(16) unsigned Al2[16 * KLD];
    __shared__ __align__(16) unsigned Bh2[16 * KLD];
    __shared__ __align__(16) unsigned Bl2[16 * KLD];

    const int tid  = threadIdx.x;
    const int m0   = blockIdx.y * 128;
    const int n0   = blockIdx.x * 128;
    const int lane = tid & 31;
    const int wid  = tid >> 5;
    const int wm   = wid & 1;
    const int wn   = wid >> 1;
    const int g    = lane >> 2;
    const int t    = lane & 3;

    float acc[4][4][4];
#pragma unroll
    for (int i = 0; i < 4; ++i)
#pragma unroll
        for (int j = 0; j < 4; ++j)
#pragma unroll
            for (int r = 0; r < 4; ++r) acc[i][j][r] = 0.f;

    for (int k0 = 0; k0 < EMB; k0 += 32) {
        __syncthreads();

#pragma unroll
        for (int u = 0; u < 4; ++u) {
            int id = tid + 256 * u;
            int r  = id >> 3;
            int c4 = (id & 7) * 4;
            float4 v = *(const float4*)(X + (size_t)(m0 + r) * EMB + k0 + c4);
            unsigned h0, l0, h1, l1;
            split2(v.x, v.y, h0, l0);
            split2(v.z, v.w, h1, l1);
            int k2 = c4 >> 1;
            Ah2[k2 * KLD + r]       = h0;
            Ah2[(k2 + 1) * KLD + r] = h1;
            Al2[k2 * KLD + r]       = l0;
            Al2[(k2 + 1) * KLD + r] = l1;
        }

#pragma unroll
        for (int u = 0; u < 2; ++u) {
            int id = tid + 256 * u;
            int k2 = id >> 5;
            int n4 = (id & 31) * 4;
            float4 w0 = *(const float4*)(W + (size_t)(k0 + 2 * k2) * EMB + n0 + n4);
            float4 w1 = *(const float4*)(W + (size_t)(k0 + 2 * k2 + 1) * EMB + n0 + n4);
            unsigned hh[4], ll[4];
            unsigned short ha, la, hb, lb;
            splitf(w0.x, ha, la); splitf(w1.x, hb, lb);
            hh[0] = (unsigned)ha | ((unsigned)hb << 16);
            ll[0] = (unsigned)la | ((unsigned)lb << 16);
            splitf(w0.y, ha, la); splitf(w1.y, hb, lb);
            hh[1] = (unsigned)ha | ((unsigned)hb << 16);
            ll[1] = (unsigned)la | ((unsigned)lb << 16);
            splitf(w0.z, ha, la); splitf(w1.z, hb, lb);
            hh[2] = (unsigned)ha | ((unsigned)hb << 16);
            ll[2] = (unsigned)la | ((unsigned)lb << 16);
            splitf(w0.w, ha, la); splitf(w1.w, hb, lb);
            hh[3] = (unsigned)ha | ((unsigned)hb << 16);
            ll[3] = (unsigned)la | ((unsigned)lb << 16);
            *(uint4*)(&Bh2[k2 * KLD + n4]) = make_uint4(hh[0], hh[1], hh[2], hh[3]);
            *(uint4*)(&Bl2[k2 * KLD + n4]) = make_uint4(ll[0], ll[1], ll[2], ll[3]);
        }
        __syncthreads();

#pragma unroll
        for (int ks = 0; ks < 2; ++ks) {
            const int kb = ks * 8 + t;
            unsigned bh0[4], bh1[4], bl0[4], bl1[4];
#pragma unroll
            for (int nt = 0; nt < 4; ++nt) {
                int cc = wn * 32 + nt * 8 + g;
                bh0[nt] = Bh2[kb * KLD + cc];
                bh1[nt] = Bh2[(kb + 4) * KLD + cc];
                bl0[nt] = Bl2[kb * KLD + cc];
                bl1[nt] = Bl2[(kb + 4) * KLD + cc];
            }
#pragma unroll
            for (int mt = 0; mt < 4; ++mt) {
                int mr = wm * 64 + mt * 16 + g;
                unsigned a0h = Ah2[kb * KLD + mr];
                unsigned a1h = Ah2[kb * KLD + mr + 8];
                unsigned a2h = Ah2[(kb + 4) * KLD + mr];
                unsigned a3h = Ah2[(kb + 4) * KLD + mr + 8];
                unsigned a0l = Al2[kb * KLD + mr];
                unsigned a1l = Al2[kb * KLD + mr + 8];
                unsigned a2l = Al2[(kb + 4) * KLD + mr];
                unsigned a3l = Al2[(kb + 4) * KLD + mr + 8];
#pragma unroll
                for (int nt = 0; nt < 4; ++nt) {
                    mma_bf16(acc[mt][nt], a0h, a1h, a2h, a3h, bh0[nt], bh1[nt]);
                    mma_bf16(acc[mt][nt], a0h, a1h, a2h, a3h, bl0[nt], bl1[nt]);
                    mma_bf16(acc[mt][nt], a0l, a1l, a2l, a3l, bh0[nt], bh1[nt]);
                }
            }
        }
    }

    // ---- Epilogue ----
#pragma unroll
    for (int mt = 0; mt < 4; ++mt) {
#pragma unroll
        for (int nt = 0; nt < 4; ++nt) {
            const int row0 = m0 + wm * 64 + mt * 16 + g;
            const int col  = n0 + wn * 32 + nt * 8 + t * 2;
            const float b0v = __ldg(&bias[col]);
            const float b1v = __ldg(&bias[col + 1]);
#pragma unroll
            for (int half = 0; half < 2; ++half) {
                const int row = row0 + half * 8;
                float vx = (acc[mt][nt][half * 2 + 0] + b0v) * oscale;
                float vy = (acc[mt][nt][half * 2 + 1] + b1v) * oscale;
                if (MODE == 0) {
                    unsigned* outh = (unsigned*)out_a;
                    unsigned* outl = (unsigned*)out_b;
                    const int b  = row >> 11;
                    const int n  = row & (SEQ - 1);
                    const int h  = col >> 6;
                    const int d2 = (col & (HD - 1)) >> 1;
                    unsigned hp, lp;
                    split2(vx, vy, hp, lp);
                    size_t idx = ((size_t)(b * HEADS + h) * SEQ + n) * 32 + d2;
                    outh[idx] = hp;
                    outl[idx] = lp;
                } else if (MODE == 1) {
                    float* out = (float*)out_a;
                    const int b  = row >> 11;
                    const int n  = row & (SEQ - 1);
                    const int h  = col >> 6;
                    const int dd = col & (HD - 1);
                    float2 v; v.x = vx; v.y = vy;
                    *(float2*)(out + ((size_t)(b * HEADS + h) * SEQ + n) * HD + dd) = v;
                } else {
                    float* out = (float*)out_a;
                    float2 v; v.x = vx; v.y = vy;
                    *(float2*)(out + (size_t)row * EMB + col) = v;
                }
            }
        }
    }
}

// ---------------------------------------------------------------------------
// Flash attention: pre-split inputs, cp.async double-buffered K/V tiles.
// Warp = 16 q-rows; Q fragments from GMEM; only P is split in-loop.
// smem per buffer: kh/kl [key][d2] stride 36; vh/vl [d][k2] stride 36.
// ---------------------------------------------------------------------------
#define KVS 2304   // 64*36 u32 per array

__global__ __launch_bounds__(256)
void attn_mma_kernel(const unsigned* __restrict__ Qh, const unsigned* __restrict__ Ql,
                     const unsigned* __restrict__ Kh, const unsigned* __restrict__ Kl,
                     const unsigned* __restrict__ Vh, const unsigned* __restrict__ Vl,
                     float* __restrict__ ctx)
{
    extern __shared__ __align__(16) unsigned dynsm[];

    const int tid  = threadIdx.x;
    const int w    = tid >> 5;
    const int lane = tid & 31;
    const int g    = lane >> 2;
    const int t    = lane & 3;
    const int bh   = blockIdx.y;
    const int q0   = blockIdx.x * 128;

    const unsigned* Qhb = Qh + (size_t)bh * SEQ * 32;
    const unsigned* Qlb = Ql + (size_t)bh * SEQ * 32;
    const unsigned* Khb = Kh + (size_t)bh * SEQ * 32;
    const unsigned* Klb = Kl + (size_t)bh * SEQ * 32;
    const unsigned* Vhb = Vh + (size_t)bh * HD * (SEQ / 2);
    const unsigned* Vlb = Vl + (size_t)bh * HD * (SEQ / 2);

    // Q fragments straight from GMEM (scale pre-folded by proj)
    unsigned qh[4][4], ql[4][4];
    const int r1 = q0 + w * 16 + g;
    const int r2 = r1 + 8;
#pragma unroll
    for (int ks = 0; ks < 4; ++ks) {
        int c0 = ks * 8 + t;
        qh[ks][0] = Qhb[(size_t)r1 * 32 + c0];
        qh[ks][1] = Qhb[(size_t)r2 * 32 + c0];
        qh[ks][2] = Qhb[(size_t)r1 * 32 + c0 + 4];
        qh[ks][3] = Qhb[(size_t)r2 * 32 + c0 + 4];
        ql[ks][0] = Qlb[(size_t)r1 * 32 + c0];
        ql[ks][1] = Qlb[(size_t)r2 * 32 + c0];
        ql[ks][2] = Qlb[(size_t)r1 * 32 + c0 + 4];
        ql[ks][3] = Qlb[(size_t)r2 * 32 + c0 + 4];
    }

    auto stage = [&](int buf, int kt) {
        unsigned* base = dynsm + buf * 4 * KVS;
#pragma unroll
        for (int u = 0; u < 4; ++u) {
            int id = tid + 256 * u;
            const unsigned* src = (id < 512) ? Khb : Klb;
            unsigned* dst = base + ((id < 512) ? 0 : KVS);
            int rem = id & 511;
            int key = rem >> 3, ch = (rem & 7) * 4;
            cp_async16(smem_u32addr(dst + key * 36 + ch),
                       src + (size_t)(kt + key) * 32 + ch);
        }
#pragma unroll
        for (int u = 0; u < 4; ++u) {
            int id = tid + 256 * u;
            const unsigned* src = (id < 512) ? Vhb : Vlb;
            unsigned* dst = base + 2 * KVS + ((id < 512) ? 0 : KVS);
            int rem = id & 511;
            int d = rem >> 3, ch = (rem & 7) * 4;
            cp_async16(smem_u32addr(dst + d * 36 + ch),
                       src + (size_t)d * (SEQ / 2) + (kt >> 1) + ch);
        }
        cp_commit();
    };

    float oacc[8][4];
#pragma unroll
    for (int j = 0; j < 8; ++j)
#pragma unroll
        for (int r = 0; r < 4; ++r) oacc[j][r] = 0.f;
    float m1 = -1e30f, m2 = -1e30f, l1s = 0.f, l2s = 0.f;

    stage(0, 0);

    const int NT = SEQ / 64;
    for (int it = 0; it < NT; ++it) {
        if (it + 1 < NT) {
            stage((it + 1) & 1, (it + 1) * 64);
            cp_wait<1>();
        } else {
            cp_wait<0>();
        }
        __syncthreads();

        const unsigned* kh = dynsm + (it & 1) * 4 * KVS;
        const unsigned* kl = kh + KVS;
        const unsigned* vh = kh + 2 * KVS;
        const unsigned* vl = kh + 3 * KVS;

        // ---- S-GEMM ----
        float sacc[8][4];
#pragma unroll
        for (int j = 0; j < 8; ++j)
#pragma unroll
            for (int r = 0; r < 4; ++r) sacc[j][r] = 0.f;

#pragma unroll
        for (int ks = 0; ks < 4; ++ks) {
#pragma unroll
            for (int j = 0; j < 8; ++j) {
                int ka = (8 * j + g) * 36 + ks * 8 + t;
                unsigned bh0 = kh[ka], bh1 = kh[ka + 4];
                unsigned bl0 = kl[ka], bl1 = kl[ka + 4];
                mma_bf16(sacc[j], qh[ks][0], qh[ks][1], qh[ks][2], qh[ks][3], bh0, bh1);
                mma_bf16(sacc[j], qh[ks][0], qh[ks][1], qh[ks][2], qh[ks][3], bl0, bl1);
                mma_bf16(sacc[j], ql[ks][0], ql[ks][1], ql[ks][2], ql[ks][3], bh0, bh1);
            }
        }

        // ---- Online softmax (rows g, g+8) ----
        float cm1 = -1e30f, cm2 = -1e30f;
#pragma unroll
        for (int j = 0; j < 8; ++j) {
            cm1 = fmaxf(cm1, fmaxf(sacc[j][0], sacc[j][1]));
            cm2 = fmaxf(cm2, fmaxf(sacc[j][2], sacc[j][3]));
        }
        cm1 = fmaxf(cm1, __shfl_xor_sync(0xffffffffu, cm1, 1));
        cm1 = fmaxf(cm1, __shfl_xor_sync(0xffffffffu, cm1, 2));
        cm2 = fmaxf(cm2, __shfl_xor_sync(0xffffffffu, cm2, 1));
        cm2 = fmaxf(cm2, __shfl_xor_sync(0xffffffffu, cm2, 2));
        const float mn1 = fmaxf(m1, cm1);
        const float mn2 = fmaxf(m2, cm2);
        const float f1 = __expf(m1 - mn1);
        const float f2 = __expf(m2 - mn2);
        m1 = mn1; m2 = mn2;

        float sp1 = 0.f, sp2 = 0.f;
#pragma unroll
        for (int j = 0; j < 8; ++j) {
            sacc[j][0] = __expf(sacc[j][0] - mn1);
            sacc[j][1] = __expf(sacc[j][1] - mn1);
            sacc[j][2] = __expf(sacc[j][2] - mn2);
            sacc[j][3] = __expf(sacc[j][3] - mn2);
            sp1 += sacc[j][0] + sacc[j][1];
            sp2 += sacc[j][2] + sacc[j][3];
        }
        sp1 += __shfl_xor_sync(0xffffffffu, sp1, 1);
        sp1 += __shfl_xor_sync(0xffffffffu, sp1, 2);
        sp2 += __shfl_xor_sync(0xffffffffu, sp2, 1);
        sp2 += __shfl_xor_sync(0xffffffffu, sp2, 2);
        l1s = l1s * f1 + sp1;
        l2s = l2s * f2 + sp2;

#pragma unroll
        for (int j = 0; j < 8; ++j) {
            oacc[j][0] *= f1; oacc[j][1] *= f1;
            oacc[j][2] *= f2; oacc[j][3] *= f2;
        }

        // ---- PV-GEMM ----
#pragma unroll
        for (int s = 0; s < 4; ++s) {
            unsigned a0h, a0l, a1h, a1l, a2h, a2l, a3h, a3l;
            split2(sacc[2 * s][0],     sacc[2 * s][1],     a0h, a0l);
            split2(sacc[2 * s][2],     sacc[2 * s][3],     a1h, a1l);
            split2(sacc[2 * s + 1][0], sacc[2 * s + 1][1], a2h, a2l);
            split2(sacc[2 * s + 1][2], sacc[2 * s + 1][3], a3h, a3l);
#pragma unroll
            for (int j = 0; j < 8; ++j) {
                int va = (8 * j + g) * 36 + 8 * s + t;
                unsigned vh0 = vh[va], vh1 = vh[va + 4];
                unsigned vl0 = vl[va], vl1 = vl[va + 4];
                mma_bf16(oacc[j], a0h, a1h, a2h, a3h, vh0, vh1);
                mma_bf16(oacc[j], a0h, a1h, a2h, a3h, vl0, vl1);
                mma_bf16(oacc[j], a0l, a1l, a2l, a3l, vh0, vh1);
            }
        }
        __syncthreads();
    }

    // ---- Epilogue ----
    const float inv1 = 1.f / l1s;
    const float inv2 = 1.f / l2s;
    const int b = bh >> 4;
    const int h = bh & 15;
#pragma unroll
    for (int j = 0; j < 8; ++j) {
        const int col = h * HD + 8 * j + 2 * t;
        float2 v1w, v2w;
        v1w.x = oacc[j][0] * inv1; v1w.y = oacc[j][1] * inv1;
        v2w.x = oacc[j][2] * inv2; v2w.y = oacc[j][3] * inv2;
        *(float2*)(ctx + (size_t)(b * SEQ + r1) * EMB + col) = v1w;
        *(float2*)(ctx + (size_t)(b * SEQ + r2) * EMB + col) = v2w;
    }
}

// ---------------------------------------------------------------------------
// Launch
// ---------------------------------------------------------------------------
extern "C" void kernel_launch(void* const* d_in, const int* in_sizes, int n_in,
                              void* d_out, int out_size)
{
    const float* x  = (const float*)d_in[0];
    const float* Wq = (const float*)d_in[1];
    const float* bq = (const float*)d_in[2];
    const float* Wk = (const float*)d_in[3];
    const float* bk = (const float*)d_in[4];
    const float* Wv = (const float*)d_in[5];
    const float* bv = (const float*)d_in[6];
    const float* Wo = (const float*)d_in[7];
    const float* bo = (const float*)d_in[8];
    float* out = (float*)d_out;

    unsigned *Qh, *Ql, *Kh, *Kl, *Vth, *Vtl;
    float *Vp, *Cp;
    cudaGetSymbolAddress((void**)&Qh,  g_Qh);
    cudaGetSymbolAddress((void**)&Ql,  g_Ql);
    cudaGetSymbolAddress((void**)&Kh,  g_Kh);
    cudaGetSymbolAddress((void**)&Kl,  g_Kl);
    cudaGetSymbolAddress((void**)&Vth, g_Vth);
    cudaGetSymbolAddress((void**)&Vtl, g_Vtl);
    cudaGetSymbolAddress((void**)&Vp,  g_V);
    cudaGetSymbolAddress((void**)&Cp,  g_ctx);

    const int attn_smem = 2 * 4 * KVS * 4;   // 73728 bytes
    static int configured = 0;
    if (!configured) {
        cudaFuncSetAttribute(attn_mma_kernel,
                             cudaFuncAttributeMaxDynamicSharedMemorySize,
                             attn_smem);
        configured = 1;
    }

    dim3 pgrid(EMB / 128, M_TOT / 128);
    proj_mma_kernel<0><<<pgrid, 256>>>(x, Wq, bq, Qh, Ql, 0.03125f);
    proj_mma_kernel<0><<<pgrid, 256>>>(x, Wk, bk, Kh, Kl, 1.0f);
    proj_mma_kernel<1><<<pgrid, 256>>>(x, Wv, bv, Vp, nullptr, 1.0f);
    split_v_t<<<dim3(SEQ / 64, BH), 256>>>(Vp, Vth, Vtl);

    dim3 agrid(SEQ / 128, BH);
    attn_mma_kernel<<<agrid, 256, attn_smem>>>(Qh, Ql, Kh, Kl, Vth, Vtl, Cp);

    proj_mma_kernel<2><<<pgrid, 256>>>(Cp, Wo, bo, out, nullptr, 1.0f);
}

// round 9
// speedup vs baseline: 1.5673x; 1.0146x over previous
#include <cuda_runtime.h>
#include <cuda_bf16.h>
#include <math_constants.h>
#include <cstdint>

// Problem constants
#define EMB   1024
#define HEADS 16
#define HD    64
#define BATCH 2
#define SEQ   2048
#define M_TOT (BATCH * SEQ)
#define BH    (BATCH * HEADS)

// Scratch (allocation-free rule)
__device__ __align__(16) unsigned g_Xh[(size_t)M_TOT * 512];   // [m][k2] row-major split
__device__ __align__(16) unsigned g_Xl[(size_t)M_TOT * 512];
__device__ __align__(16) unsigned g_Wth[4][(size_t)EMB * 512]; // [n][k2] transposed split
__device__ __align__(16) unsigned g_Wtl[4][(size_t)EMB * 512];
__device__ __align__(16) unsigned g_Qh[(size_t)BH * SEQ * 32]; // [bh][n][d2]
__device__ __align__(16) unsigned g_Ql[(size_t)BH * SEQ * 32];
__device__ __align__(16) unsigned g_Kh[(size_t)BH * SEQ * 32];
__device__ __align__(16) unsigned g_Kl[(size_t)BH * SEQ * 32];
__device__ __align__(16) float    g_V [(size_t)BH * SEQ * HD];
__device__ __align__(16) unsigned g_Vth[(size_t)BH * HD * (SEQ / 2)];
__device__ __align__(16) unsigned g_Vtl[(size_t)BH * HD * (SEQ / 2)];
__device__ __align__(16) float    g_ctx[(size_t)M_TOT * EMB];

// ---------------------------------------------------------------------------
// Helpers
// ---------------------------------------------------------------------------
__device__ __forceinline__ void splitf(float v, unsigned short& h, unsigned short& l)
{
    __nv_bfloat16 hb = __float2bfloat16(v);
    float rv = v - __bfloat162float(hb);
    __nv_bfloat16 lb = __float2bfloat16(rv);
    h = ((__nv_bfloat16_raw)hb).x;
    l = ((__nv_bfloat16_raw)lb).x;
}

__device__ __forceinline__ void split2(float v0, float v1,
                                       unsigned& hp, unsigned& lp)
{
    unsigned short h0, l0, h1, l1;
    splitf(v0, h0, l0);
    splitf(v1, h1, l1);
    hp = (unsigned)h0 | ((unsigned)h1 << 16);
    lp = (unsigned)l0 | ((unsigned)l1 << 16);
}

__device__ __forceinline__ void mma_bf16(float* d,
                                         unsigned a0, unsigned a1,
                                         unsigned a2, unsigned a3,
                                         unsigned b0, unsigned b1)
{
    asm volatile(
        "mma.sync.aligned.m16n8k16.row.col.f32.bf16.bf16.f32 "
        "{%0,%1,%2,%3}, {%4,%5,%6,%7}, {%8,%9}, {%0,%1,%2,%3};\n"
        : "+f"(d[0]), "+f"(d[1]), "+f"(d[2]), "+f"(d[3])
        : "r"(a0), "r"(a1), "r"(a2), "r"(a3), "r"(b0), "r"(b1));
}

__device__ __forceinline__ unsigned smem_u32addr(const void* p)
{
    return (unsigned)__cvta_generic_to_shared(p);
}
__device__ __forceinline__ void cp_async16(unsigned dst, const void* src)
{
    asm volatile("cp.async.cg.shared.global [%0], [%1], 16;\n" :: "r"(dst), "l"(src));
}
__device__ __forceinline__ void cp_commit()
{
    asm volatile("cp.async.commit_group;\n");
}
template <int N>
__device__ __forceinline__ void cp_wait()
{
    asm volatile("cp.async.wait_group %0;\n" :: "n"(N));
}

// ---------------------------------------------------------------------------
// Prologue: fp32 [m][1024] -> row-major split u32 [m][512]. grid 8192 x 256.
// ---------------------------------------------------------------------------
__global__ void split_rows(const float* __restrict__ in,
                           unsigned* __restrict__ outh,
                           unsigned* __restrict__ outl)
{
    const size_t id = (size_t)blockIdx.x * 256 + threadIdx.x;
    float2 v = *(const float2*)(in + 2 * id);
    unsigned hp, lp;
    split2(v.x, v.y, hp, lp);
    outh[id] = hp;
    outl[id] = lp;
}

// W fp32 [k][n] -> transposed split [n][k2]. grid (16 kb, 16 nb), 256 thr.
__global__ void transpose_split_w(const float* __restrict__ W,
                                  unsigned* __restrict__ outh,
                                  unsigned* __restrict__ outl)
{
    __shared__ float tile[64][65];
    const int tid = threadIdx.x;
    const int kb  = blockIdx.x * 64;
    const int nb  = blockIdx.y * 64;
#pragma unroll
    for (int u = 0; u < 16; ++u) {
        int id = tid + 256 * u;
        int kk = id >> 6, nn = id & 63;
        tile[kk][nn] = W[(size_t)(kb + kk) * EMB + nb + nn];
    }
    __syncthreads();
#pragma unroll
    for (int u = 0; u < 8; ++u) {
        int id = tid + 256 * u;
        int nn = id >> 5, k2 = id & 31;
        unsigned hp, lp;
        split2(tile[2 * k2][nn], tile[2 * k2 + 1][nn], hp, lp);
        size_t o = (size_t)(nb + nn) * 512 + (kb >> 1) + k2;
        outh[o] = hp;
        outl[o] = lp;
    }
}

// V fp32 [bh][n][d] -> transposed split [bh][d][n2]. grid (SEQ/64, BH), 256 thr.
__global__ void split_v_t(const float* __restrict__ V,
                          unsigned* __restrict__ outh,
                          unsigned* __restrict__ outl)
{
    __shared__ float tile[64][65];
    const int tid  = threadIdx.x;
    const int bh   = blockIdx.y;
    const int nblk = blockIdx.x * 64;
    const float* src = V + (size_t)bh * SEQ * HD + (size_t)nblk * HD;
#pragma unroll
    for (int u = 0; u < 16; ++u) {
        int id = tid + 256 * u;
        int n = id >> 6, d = id & 63;
        tile[n][d] = src[n * HD + d];
    }
    __syncthreads();
    unsigned* oh = outh + (size_t)bh * HD * (SEQ / 2) + (nblk >> 1);
    unsigned* ol = outl + (size_t)bh * HD * (SEQ / 2) + (nblk >> 1);
#pragma unroll
    for (int u = 0; u < 8; ++u) {
        int id = tid + 256 * u;
        int d = id >> 5, n2 = id & 31;
        unsigned hp, lp;
        split2(tile[2 * n2][d], tile[2 * n2 + 1][d], hp, lp);
        oh[(size_t)d * (SEQ / 2) + n2] = hp;
        ol[(size_t)d * (SEQ / 2) + n2] = lp;
    }
}

// ---------------------------------------------------------------------------
// Projection GEMM (mma.sync, pre-split inputs, cp.async double-buffered).
// A tiles [row][k2] stride 20 (conflict-free fragments), B tiles likewise.
// MODE 0: split head-major out (Q/K). MODE 1: fp32 head-major (V).
// MODE 2: fp32 row-major (final).
// ---------------------------------------------------------------------------
#define PSTR 20                     // u32 stride per tile row
#define ARR  (128 * PSTR)           // 2560 u32 per array
#define PBUF (4 * ARR)              // 10240 u32 per buffer (40960 B)

template <int MODE>
__global__ __launch_bounds__(256, 2)
void proj_mma_kernel(const unsigned* __restrict__ Ah_rows,
                     const unsigned* __restrict__ Al_rows,
                     const unsigned* __restrict__ Bh_rows,
                     const unsigned* __restrict__ Bl_rows,
                     const float* __restrict__ bias,
                     void* __restrict__ out_a,
                     void* __restrict__ out_b,
                     float oscale)
{
    extern __shared__ __align__(16) unsigned psm[];

    const int tid  = threadIdx.x;
    const int m0   = blockIdx.y * 128;
    const int n0   = blockIdx.x * 128;
    const int lane = tid & 31;
    const int wid  = tid >> 5;
    const int wm   = wid & 1;
    const int wn   = wid >> 1;
    const int g    = lane >> 2;
    const int t    = lane & 3;

    const unsigned* a_h = Ah_rows + (size_t)m0 * 512;
    const unsigned* a_l = Al_rows + (size_t)m0 * 512;
    const unsigned* b_h = Bh_rows + (size_t)n0 * 512;
    const unsigned* b_l = Bl_rows + (size_t)n0 * 512;

    // Stage one 32-k chunk (16 k2) of all four tiles into buffer `buf`.
    auto stage = [&](int buf, int c) {
        unsigned* base = psm + buf * PBUF;
#pragma unroll
        for (int u = 0; u < 8; ++u) {
            int id  = tid + 256 * u;            // 2048 chunks
            int arr = id >> 9;                  // 0:Ah 1:Al 2:Bh 3:Bl
            int rem = id & 511;
            int row = rem >> 2;
            int ch  = (rem & 3) * 4;
            const unsigned* src = (arr == 0) ? a_h : (arr == 1) ? a_l
                                : (arr == 2) ? b_h : b_l;
            cp_async16(smem_u32addr(base + arr * ARR + row * PSTR + ch),
                       src + (size_t)row * 512 + c * 16 + ch);
        }
        cp_commit();
    };

    float acc[4][4][4];
#pragma unroll
    for (int i = 0; i < 4; ++i)
#pragma unroll
        for (int j = 0; j < 4; ++j)
#pragma unroll
            for (int r = 0; r < 4; ++r) acc[i][j][r] = 0.f;

    stage(0, 0);

    for (int c = 0; c < 32; ++c) {
        if (c + 1 < 32) {
            stage((c + 1) & 1, c + 1);
            cp_wait<1>();
        } else {
            cp_wait<0>();
        }
        __syncthreads();

        const unsigned* Ah2 = psm + (c & 1) * PBUF;
        const unsigned* Al2 = Ah2 + ARR;
        const unsigned* Bh2 = Ah2 + 2 * ARR;
        const unsigned* Bl2 = Ah2 + 3 * ARR;

#pragma unroll
        for (int ks = 0; ks < 2; ++ks) {
            const int kb = ks * 8 + t;
            unsigned bh0[4], bh1[4], bl0[4], bl1[4];
#pragma unroll
            for (int nt = 0; nt < 4; ++nt) {
                int cc = wn * 32 + nt * 8 + g;
                bh0[nt] = Bh2[cc * PSTR + kb];
                bh1[nt] = Bh2[cc * PSTR + kb + 4];
                bl0[nt] = Bl2[cc * PSTR + kb];
                bl1[nt] = Bl2[cc * PSTR + kb + 4];
            }
#pragma unroll
            for (int mt = 0; mt < 4; ++mt) {
                int mr = wm * 64 + mt * 16 + g;
                unsigned a0h = Ah2[mr * PSTR + kb];
                unsigned a1h = Ah2[(mr + 8) * PSTR + kb];
                unsigned a2h = Ah2[mr * PSTR + kb + 4];
                unsigned a3h = Ah2[(mr + 8) * PSTR + kb + 4];
                unsigned a0l = Al2[mr * PSTR + kb];
                unsigned a1l = Al2[(mr + 8) * PSTR + kb];
                unsigned a2l = Al2[mr * PSTR + kb + 4];
                unsigned a3l = Al2[(mr + 8) * PSTR + kb + 4];
#pragma unroll
                for (int nt = 0; nt < 4; ++nt) {
                    mma_bf16(acc[mt][nt], a0h, a1h, a2h, a3h, bh0[nt], bh1[nt]);
                    mma_bf16(acc[mt][nt], a0h, a1h, a2h, a3h, bl0[nt], bl1[nt]);
                    mma_bf16(acc[mt][nt], a0l, a1l, a2l, a3l, bh0[nt], bh1[nt]);
                }
            }
        }
        __syncthreads();
    }

    // ---- Epilogue ----
#pragma unroll
    for (int mt = 0; mt < 4; ++mt) {
#pragma unroll
        for (int nt = 0; nt < 4; ++nt) {
            const int row0 = m0 + wm * 64 + mt * 16 + g;
            const int col  = n0 + wn * 32 + nt * 8 + t * 2;
            const float b0v = __ldg(&bias[col]);
            const float b1v = __ldg(&bias[col + 1]);
#pragma unroll
            for (int half = 0; half < 2; ++half) {
                const int row = row0 + half * 8;
                float vx = (acc[mt][nt][half * 2 + 0] + b0v) * oscale;
                float vy = (acc[mt][nt][half * 2 + 1] + b1v) * oscale;
                if (MODE == 0) {
                    unsigned* outh = (unsigned*)out_a;
                    unsigned* outl = (unsigned*)out_b;
                    const int b  = row >> 11;
                    const int n  = row & (SEQ - 1);
                    const int h  = col >> 6;
                    const int d2 = (col & (HD - 1)) >> 1;
                    unsigned hp, lp;
                    split2(vx, vy, hp, lp);
                    size_t idx = ((size_t)(b * HEADS + h) * SEQ + n) * 32 + d2;
                    outh[idx] = hp;
                    outl[idx] = lp;
                } else if (MODE == 1) {
                    float* out = (float*)out_a;
                    const int b  = row >> 11;
                    const int n  = row & (SEQ - 1);
                    const int h  = col >> 6;
                    const int dd = col & (HD - 1);
                    float2 v; v.x = vx; v.y = vy;
                    *(float2*)(out + ((size_t)(b * HEADS + h) * SEQ + n) * HD + dd) = v;
                } else {
                    float* out = (float*)out_a;
                    float2 v; v.x = vx; v.y = vy;
                    *(float2*)(out + (size_t)row * EMB + col) = v;
                }
            }
        }
    }
}

// ---------------------------------------------------------------------------
// Flash attention (unchanged from R7): pre-split inputs, cp.async double-buffer.
// ---------------------------------------------------------------------------
#define KVS 2304

__global__ __launch_bounds__(256)
void attn_mma_kernel(const unsigned* __restrict__ Qh, const unsigned* __restrict__ Ql,
                     const unsigned* __restrict__ Kh, const unsigned* __restrict__ Kl,
                     const unsigned* __restrict__ Vh, const unsigned* __restrict__ Vl,
                     float* __restrict__ ctx)
{
    extern __shared__ __align__(16) unsigned dynsm[];

    const int tid  = threadIdx.x;
    const int w    = tid >> 5;
    const int lane = tid & 31;
    const int g    = lane >> 2;
    const int t    = lane & 3;
    const int bh   = blockIdx.y;
    const int q0   = blockIdx.x * 128;

    const unsigned* Qhb = Qh + (size_t)bh * SEQ * 32;
    const unsigned* Qlb = Ql + (size_t)bh * SEQ * 32;
    const unsigned* Khb = Kh + (size_t)bh * SEQ * 32;
    const unsigned* Klb = Kl + (size_t)bh * SEQ * 32;
    const unsigned* Vhb = Vh + (size_t)bh * HD * (SEQ / 2);
    const unsigned* Vlb = Vl + (size_t)bh * HD * (SEQ / 2);

    unsigned qh[4][4], ql[4][4];
    const int r1 = q0 + w * 16 + g;
    const int r2 = r1 + 8;
#pragma unroll
    for (int ks = 0; ks < 4; ++ks) {
        int c0 = ks * 8 + t;
        qh[ks][0] = Qhb[(size_t)r1 * 32 + c0];
        qh[ks][1] = Qhb[(size_t)r2 * 32 + c0];
        qh[ks][2] = Qhb[(size_t)r1 * 32 + c0 + 4];
        qh[ks][3] = Qhb[(size_t)r2 * 32 + c0 + 4];
        ql[ks][0] = Qlb[(size_t)r1 * 32 + c0];
        ql[ks][1] = Qlb[(size_t)r2 * 32 + c0];
        ql[ks][2] = Qlb[(size_t)r1 * 32 + c0 + 4];
        ql[ks][3] = Qlb[(size_t)r2 * 32 + c0 + 4];
    }

    auto stage = [&](int buf, int kt) {
        unsigned* base = dynsm + buf * 4 * KVS;
#pragma unroll
        for (int u = 0; u < 4; ++u) {
            int id = tid + 256 * u;
            const unsigned* src = (id < 512) ? Khb : Klb;
            unsigned* dst = base + ((id < 512) ? 0 : KVS);
            int rem = id & 511;
            int key = rem >> 3, ch = (rem & 7) * 4;
            cp_async16(smem_u32addr(dst + key * 36 + ch),
                       src + (size_t)(kt + key) * 32 + ch);
        }
#pragma unroll
        for (int u = 0; u < 4; ++u) {
            int id = tid + 256 * u;
            const unsigned* src = (id < 512) ? Vhb : Vlb;
            unsigned* dst = base + 2 * KVS + ((id < 512) ? 0 : KVS);
            int rem = id & 511;
            int d = rem >> 3, ch = (rem & 7) * 4;
            cp_async16(smem_u32addr(dst + d * 36 + ch),
                       src + (size_t)d * (SEQ / 2) + (kt >> 1) + ch);
        }
        cp_commit();
    };

    float oacc[8][4];
#pragma unroll
    for (int j = 0; j < 8; ++j)
#pragma unroll
        for (int r = 0; r < 4; ++r) oacc[j][r] = 0.f;
    float m1 = -1e30f, m2 = -1e30f, l1s = 0.f, l2s = 0.f;

    stage(0, 0);

    const int NT = SEQ / 64;
    for (int it = 0; it < NT; ++it) {
        if (it + 1 < NT) {
            stage((it + 1) & 1, (it + 1) * 64);
            cp_wait<1>();
        } else {
            cp_wait<0>();
        }
        __syncthreads();

        const unsigned* kh = dynsm + (it & 1) * 4 * KVS;
        const unsigned* kl = kh + KVS;
        const unsigned* vh = kh + 2 * KVS;
        const unsigned* vl = kh + 3 * KVS;

        float sacc[8][4];
#pragma unroll
        for (int j = 0; j < 8; ++j)
#pragma unroll
            for (int r = 0; r < 4; ++r) sacc[j][r] = 0.f;

#pragma unroll
        for (int ks = 0; ks < 4; ++ks) {
#pragma unroll
            for (int j = 0; j < 8; ++j) {
                int ka = (8 * j + g) * 36 + ks * 8 + t;
                unsigned bh0 = kh[ka], bh1 = kh[ka + 4];
                unsigned bl0 = kl[ka], bl1 = kl[ka + 4];
                mma_bf16(sacc[j], qh[ks][0], qh[ks][1], qh[ks][2], qh[ks][3], bh0, bh1);
                mma_bf16(sacc[j], qh[ks][0], qh[ks][1], qh[ks][2], qh[ks][3], bl0, bl1);
                mma_bf16(sacc[j], ql[ks][0], ql[ks][1], ql[ks][2], ql[ks][3], bh0, bh1);
            }
        }

        float cm1 = -1e30f, cm2 = -1e30f;
#pragma unroll
        for (int j = 0; j < 8; ++j) {
            cm1 = fmaxf(cm1, fmaxf(sacc[j][0], sacc[j][1]));
            cm2 = fmaxf(cm2, fmaxf(sacc[j][2], sacc[j][3]));
        }
        cm1 = fmaxf(cm1, __shfl_xor_sync(0xffffffffu, cm1, 1));
        cm1 = fmaxf(cm1, __shfl_xor_sync(0xffffffffu, cm1, 2));
        cm2 = fmaxf(cm2, __shfl_xor_sync(0xffffffffu, cm2, 1));
        cm2 = fmaxf(cm2, __shfl_xor_sync(0xffffffffu, cm2, 2));
        const float mn1 = fmaxf(m1, cm1);
        const float mn2 = fmaxf(m2, cm2);
        const float f1 = __expf(m1 - mn1);
        const float f2 = __expf(m2 - mn2);
        m1 = mn1; m2 = mn2;

        float sp1 = 0.f, sp2 = 0.f;
#pragma unroll
        for (int j = 0; j < 8; ++j) {
            sacc[j][0] = __expf(sacc[j][0] - mn1);
            sacc[j][1] = __expf(sacc[j][1] - mn1);
            sacc[j][2] = __expf(sacc[j][2] - mn2);
            sacc[j][3] = __expf(sacc[j][3] - mn2);
            sp1 += sacc[j][0] + sacc[j][1];
            sp2 += sacc[j][2] + sacc[j][3];
        }
        sp1 += __shfl_xor_sync(0xffffffffu, sp1, 1);
        sp1 += __shfl_xor_sync(0xffffffffu, sp1, 2);
        sp2 += __shfl_xor_sync(0xffffffffu, sp2, 1);
        sp2 += __shfl_xor_sync(0xffffffffu, sp2, 2);
        l1s = l1s * f1 + sp1;
        l2s = l2s * f2 + sp2;

#pragma unroll
        for (int j = 0; j < 8; ++j) {
            oacc[j][0] *= f1; oacc[j][1] *= f1;
            oacc[j][2] *= f2; oacc[j][3] *= f2;
        }

#pragma unroll
        for (int s = 0; s < 4; ++s) {
            unsigned a0h, a0l, a1h, a1l, a2h, a2l, a3h, a3l;
            split2(sacc[2 * s][0],     sacc[2 * s][1],     a0h, a0l);
            split2(sacc[2 * s][2],     sacc[2 * s][3],     a1h, a1l);
            split2(sacc[2 * s + 1][0], sacc[2 * s + 1][1], a2h, a2l);
            split2(sacc[2 * s + 1][2], sacc[2 * s + 1][3], a3h, a3l);
#pragma unroll
            for (int j = 0; j < 8; ++j) {
                int va = (8 * j + g) * 36 + 8 * s + t;
                unsigned vh0 = vh[va], vh1 = vh[va + 4];
                unsigned vl0 = vl[va], vl1 = vl[va + 4];
                mma_bf16(oacc[j], a0h, a1h, a2h, a3h, vh0, vh1);
                mma_bf16(oacc[j], a0h, a1h, a2h, a3h, vl0, vl1);
                mma_bf16(oacc[j], a0l, a1l, a2l, a3l, vh0, vh1);
            }
        }
        __syncthreads();
    }

    const float inv1 = 1.f / l1s;
    const float inv2 = 1.f / l2s;
    const int b = bh >> 4;
    const int h = bh & 15;
#pragma unroll
    for (int j = 0; j < 8; ++j) {
        const int col = h * HD + 8 * j + 2 * t;
        float2 v1w, v2w;
        v1w.x = oacc[j][0] * inv1; v1w.y = oacc[j][1] * inv1;
        v2w.x = oacc[j][2] * inv2; v2w.y = oacc[j][3] * inv2;
        *(float2*)(ctx + (size_t)(b * SEQ + r1) * EMB + col) = v1w;
        *(float2*)(ctx + (size_t)(b * SEQ + r2) * EMB + col) = v2w;
    }
}

// ---------------------------------------------------------------------------
// Launch
// ---------------------------------------------------------------------------
extern "C" void kernel_launch(void* const* d_in, const int* in_sizes, int n_in,
                              void* d_out, int out_size)
{
    const float* x  = (const float*)d_in[0];
    const float* Wq = (const float*)d_in[1];
    const float* bq = (const float*)d_in[2];
    const float* Wk = (const float*)d_in[3];
    const float* bk = (const float*)d_in[4];
    const float* Wv = (const float*)d_in[5];
    const float* bv = (const float*)d_in[6];
    const float* Wo = (const float*)d_in[7];
    const float* bo = (const float*)d_in[8];
    float* out = (float*)d_out;

    unsigned *Xh, *Xl, *Wth, *Wtl, *Qh, *Ql, *Kh, *Kl, *Vth, *Vtl;
    float *Vp, *Cp;
    cudaGetSymbolAddress((void**)&Xh,  g_Xh);
    cudaGetSymbolAddress((void**)&Xl,  g_Xl);
    cudaGetSymbolAddress((void**)&Wth, g_Wth);
    cudaGetSymbolAddress((void**)&Wtl, g_Wtl);
    cudaGetSymbolAddress((void**)&Qh,  g_Qh);
    cudaGetSymbolAddress((void**)&Ql,  g_Ql);
    cudaGetSymbolAddress((void**)&Kh,  g_Kh);
    cudaGetSymbolAddress((void**)&Kl,  g_Kl);
    cudaGetSymbolAddress((void**)&Vth, g_Vth);
    cudaGetSymbolAddress((void**)&Vtl, g_Vtl);
    cudaGetSymbolAddress((void**)&Vp,  g_V);
    cudaGetSymbolAddress((void**)&Cp,  g_ctx);

    const int attn_smem = 2 * 4 * KVS * 4;   // 73728
    const int proj_smem = 2 * PBUF * 4;      // 81920
    static int configured = 0;
    if (!configured) {
        cudaFuncSetAttribute(attn_mma_kernel,
                             cudaFuncAttributeMaxDynamicSharedMemorySize, attn_smem);
        cudaFuncSetAttribute(proj_mma_kernel<0>,
                             cudaFuncAttributeMaxDynamicSharedMemorySize, proj_smem);
        cudaFuncSetAttribute(proj_mma_kernel<1>,
                             cudaFuncAttributeMaxDynamicSharedMemorySize, proj_smem);
        cudaFuncSetAttribute(proj_mma_kernel<2>,
                             cudaFuncAttributeMaxDynamicSharedMemorySize, proj_smem);
        configured = 1;
    }

    const size_t WSZ = (size_t)EMB * 512;

    // Prologue: pre-split X and all weights
    split_rows<<<8192, 256>>>(x, Xh, Xl);
    transpose_split_w<<<dim3(16, 16), 256>>>(Wq, Wth + 0 * WSZ, Wtl + 0 * WSZ);
    transpose_split_w<<<dim3(16, 16), 256>>>(Wk, Wth + 1 * WSZ, Wtl + 1 * WSZ);
    transpose_split_w<<<dim3(16, 16), 256>>>(Wv, Wth + 2 * WSZ, Wtl + 2 * WSZ);
    transpose_split_w<<<dim3(16, 16), 256>>>(Wo, Wth + 3 * WSZ, Wtl + 3 * WSZ);

    dim3 pgrid(EMB / 128, M_TOT / 128);
    proj_mma_kernel<0><<<pgrid, 256, proj_smem>>>(Xh, Xl, Wth + 0 * WSZ, Wtl + 0 * WSZ,
                                                  bq, Qh, Ql, 0.03125f);
    proj_mma_kernel<0><<<pgrid, 256, proj_smem>>>(Xh, Xl, Wth + 1 * WSZ, Wtl + 1 * WSZ,
                                                  bk, Kh, Kl, 1.0f);
    proj_mma_kernel<1><<<pgrid, 256, proj_smem>>>(Xh, Xl, Wth + 2 * WSZ, Wtl + 2 * WSZ,
                                                  bv, Vp, nullptr, 1.0f);
    split_v_t<<<dim3(SEQ / 64, BH), 256>>>(Vp, Vth, Vtl);

    dim3 agrid(SEQ / 128, BH);
    attn_mma_kernel<<<agrid, 256, attn_smem>>>(Qh, Ql, Kh, Kl, Vth, Vtl, Cp);

    // ctx -> split (reuse X buffers), then final projection
    split_rows<<<8192, 256>>>(Cp, Xh, Xl);
    proj_mma_kernel<2><<<pgrid, 256, proj_smem>>>(Xh, Xl, Wth + 3 * WSZ, Wtl + 3 * WSZ,
                                                  bo, out, nullptr, 1.0f);
}

// round 10
// speedup vs baseline: 1.6057x; 1.0245x over previous
#include <cuda_runtime.h>
#include <cuda_bf16.h>
#include <math_constants.h>
#include <cstdint>

// Problem constants
#define EMB   1024
#define HEADS 16
#define HD    64
#define BATCH 2
#define SEQ   2048
#define M_TOT (BATCH * SEQ)
#define BH    (BATCH * HEADS)
#define WSZ   ((size_t)EMB * 512)

// Scratch (allocation-free rule)
__device__ __align__(16) unsigned g_Xh[(size_t)M_TOT * 512];   // [m][k2] split (X, later ctx)
__device__ __align__(16) unsigned g_Xl[(size_t)M_TOT * 512];
__device__ __align__(16) unsigned g_Wth[4 * WSZ];              // [n][k2] transposed split
__device__ __align__(16) unsigned g_Wtl[4 * WSZ];
__device__ __align__(16) unsigned g_Qh[(size_t)BH * SEQ * 32]; // [bh][n][d2]
__device__ __align__(16) unsigned g_Ql[(size_t)BH * SEQ * 32];
__device__ __align__(16) unsigned g_Kh[(size_t)BH * SEQ * 32];
__device__ __align__(16) unsigned g_Kl[(size_t)BH * SEQ * 32];
__device__ __align__(16) float    g_V [(size_t)BH * SEQ * HD];
__device__ __align__(16) unsigned g_Vth[(size_t)BH * HD * (SEQ / 2)];
__device__ __align__(16) unsigned g_Vtl[(size_t)BH * HD * (SEQ / 2)];

// ---------------------------------------------------------------------------
// Helpers
// ---------------------------------------------------------------------------
__device__ __forceinline__ void splitf(float v, unsigned short& h, unsigned short& l)
{
    __nv_bfloat16 hb = __float2bfloat16(v);
    float rv = v - __bfloat162float(hb);
    __nv_bfloat16 lb = __float2bfloat16(rv);
    h = ((__nv_bfloat16_raw)hb).x;
    l = ((__nv_bfloat16_raw)lb).x;
}

__device__ __forceinline__ void split2(float v0, float v1,
                                       unsigned& hp, unsigned& lp)
{
    unsigned short h0, l0, h1, l1;
    splitf(v0, h0, l0);
    splitf(v1, h1, l1);
    hp = (unsigned)h0 | ((unsigned)h1 << 16);
    lp = (unsigned)l0 | ((unsigned)l1 << 16);
}

__device__ __forceinline__ void mma_bf16(float* d,
                                         unsigned a0, unsigned a1,
                                         unsigned a2, unsigned a3,
                                         unsigned b0, unsigned b1)
{
    asm volatile(
        "mma.sync.aligned.m16n8k16.row.col.f32.bf16.bf16.f32 "
        "{%0,%1,%2,%3}, {%4,%5,%6,%7}, {%8,%9}, {%0,%1,%2,%3};\n"
        : "+f"(d[0]), "+f"(d[1]), "+f"(d[2]), "+f"(d[3])
        : "r"(a0), "r"(a1), "r"(a2), "r"(a3), "r"(b0), "r"(b1));
}

__device__ __forceinline__ unsigned smem_u32addr(const void* p)
{
    return (unsigned)__cvta_generic_to_shared(p);
}
__device__ __forceinline__ void cp_async16(unsigned dst, const void* src)
{
    asm volatile("cp.async.cg.shared.global [%0], [%1], 16;\n" :: "r"(dst), "l"(src));
}
__device__ __forceinline__ void cp_commit()
{
    asm volatile("cp.async.commit_group;\n");
}
template <int N>
__device__ __forceinline__ void cp_wait()
{
    asm volatile("cp.async.wait_group %0;\n" :: "n"(N));
}

// ---------------------------------------------------------------------------
// Prologue: X fp32 [m][1024] -> row-major split [m][512]. float4/thread.
// grid 4096 x 256.
// ---------------------------------------------------------------------------
__global__ void split_rows(const float* __restrict__ in,
                           unsigned* __restrict__ outh,
                           unsigned* __restrict__ outl)
{
    const size_t id = (size_t)blockIdx.x * 256 + threadIdx.x;   // float4 index
    float4 v = ((const float4*)in)[id];
    unsigned h0, l0, h1, l1;
    split2(v.x, v.y, h0, l0);
    split2(v.z, v.w, h1, l1);
    ((uint2*)outh)[id] = make_uint2(h0, h1);
    ((uint2*)outl)[id] = make_uint2(l0, l1);
}

// All four W fp32 [k][n] -> transposed split [n][k2]. grid (16, 16, 4), 256 thr.
__global__ void split_all_w(const float* __restrict__ Wq, const float* __restrict__ Wk,
                            const float* __restrict__ Wv, const float* __restrict__ Wo,
                            unsigned* __restrict__ outh,
                            unsigned* __restrict__ outl)
{
    __shared__ float tile[64][65];
    const int tid = threadIdx.x;
    const int kb  = blockIdx.x * 64;
    const int nb  = blockIdx.y * 64;
    const int z   = blockIdx.z;
    const float* W = (z == 0) ? Wq : (z == 1) ? Wk : (z == 2) ? Wv : Wo;
    unsigned* oh = outh + (size_t)z * WSZ;
    unsigned* ol = outl + (size_t)z * WSZ;
#pragma unroll
    for (int u = 0; u < 16; ++u) {
        int id = tid + 256 * u;
        int kk = id >> 6, nn = id & 63;
        tile[kk][nn] = W[(size_t)(kb + kk) * EMB + nb + nn];
    }
    __syncthreads();
#pragma unroll
    for (int u = 0; u < 8; ++u) {
        int id = tid + 256 * u;
        int nn = id >> 5, k2 = id & 31;
        unsigned hp, lp;
        split2(tile[2 * k2][nn], tile[2 * k2 + 1][nn], hp, lp);
        size_t o = (size_t)(nb + nn) * 512 + (kb >> 1) + k2;
        oh[o] = hp;
        ol[o] = lp;
    }
}

// V fp32 [bh][n][d] -> transposed split [bh][d][n2]. grid (SEQ/64, BH), 256 thr.
__global__ void split_v_t(const float* __restrict__ V,
                          unsigned* __restrict__ outh,
                          unsigned* __restrict__ outl)
{
    __shared__ float tile[64][65];
    const int tid  = threadIdx.x;
    const int bh   = blockIdx.y;
    const int nblk = blockIdx.x * 64;
    const float* src = V + (size_t)bh * SEQ * HD + (size_t)nblk * HD;
#pragma unroll
    for (int u = 0; u < 16; ++u) {
        int id = tid + 256 * u;
        int n = id >> 6, d = id & 63;
        tile[n][d] = src[n * HD + d];
    }
    __syncthreads();
    unsigned* oh = outh + (size_t)bh * HD * (SEQ / 2) + (nblk >> 1);
    unsigned* ol = outl + (size_t)bh * HD * (SEQ / 2) + (nblk >> 1);
#pragma unroll
    for (int u = 0; u < 8; ++u) {
        int id = tid + 256 * u;
        int d = id >> 5, n2 = id & 31;
        unsigned hp, lp;
        split2(tile[2 * n2][d], tile[2 * n2 + 1][d], hp, lp);
        oh[(size_t)d * (SEQ / 2) + n2] = hp;
        ol[(size_t)d * (SEQ / 2) + n2] = lp;
    }
}

// ---------------------------------------------------------------------------
// Projection GEMM core (mma.sync, pre-split inputs, cp.async double-buffered).
// ---------------------------------------------------------------------------
#define PSTR 20
#define ARR  (128 * PSTR)
#define PBUF (4 * ARR)              // 10240 u32 (40960 B) per buffer

__device__ __forceinline__ void proj_core(const unsigned* __restrict__ a_h,
                                          const unsigned* __restrict__ a_l,
                                          const unsigned* __restrict__ b_h,
                                          const unsigned* __restrict__ b_l,
                                          unsigned* psm, float acc[4][4][4])
{
    const int tid  = threadIdx.x;
    const int lane = tid & 31;
    const int wid  = tid >> 5;
    const int wm   = wid & 1;
    const int wn   = wid >> 1;
    const int g    = lane >> 2;
    const int t    = lane & 3;

    auto stage = [&](int buf, int c) {
        unsigned* base = psm + buf * PBUF;
#pragma unroll
        for (int u = 0; u < 8; ++u) {
            int id  = tid + 256 * u;
            int arr = id >> 9;
            int rem = id & 511;
            int row = rem >> 2;
            int ch  = (rem & 3) * 4;
            const unsigned* src = (arr == 0) ? a_h : (arr == 1) ? a_l
                                : (arr == 2) ? b_h : b_l;
            cp_async16(smem_u32addr(base + arr * ARR + row * PSTR + ch),
                       src + (size_t)row * 512 + c * 16 + ch);
        }
        cp_commit();
    };

    stage(0, 0);

    for (int c = 0; c < 32; ++c) {
        if (c + 1 < 32) {
            stage((c + 1) & 1, c + 1);
            cp_wait<1>();
        } else {
            cp_wait<0>();
        }
        __syncthreads();

        const unsigned* Ah2 = psm + (c & 1) * PBUF;
        const unsigned* Al2 = Ah2 + ARR;
        const unsigned* Bh2 = Ah2 + 2 * ARR;
        const unsigned* Bl2 = Ah2 + 3 * ARR;

#pragma unroll
        for (int ks = 0; ks < 2; ++ks) {
            const int kb = ks * 8 + t;
            unsigned bh0[4], bh1[4], bl0[4], bl1[4];
#pragma unroll
            for (int nt = 0; nt < 4; ++nt) {
                int cc = wn * 32 + nt * 8 + g;
                bh0[nt] = Bh2[cc * PSTR + kb];
                bh1[nt] = Bh2[cc * PSTR + kb + 4];
                bl0[nt] = Bl2[cc * PSTR + kb];
                bl1[nt] = Bl2[cc * PSTR + kb + 4];
            }
#pragma unroll
            for (int mt = 0; mt < 4; ++mt) {
                int mr = wm * 64 + mt * 16 + g;
                unsigned a0h = Ah2[mr * PSTR + kb];
                unsigned a1h = Ah2[(mr + 8) * PSTR + kb];
                unsigned a2h = Ah2[mr * PSTR + kb + 4];
                unsigned a3h = Ah2[(mr + 8) * PSTR + kb + 4];
                unsigned a0l = Al2[mr * PSTR + kb];
                unsigned a1l = Al2[(mr + 8) * PSTR + kb];
                unsigned a2l = Al2[mr * PSTR + kb + 4];
                unsigned a3l = Al2[(mr + 8) * PSTR + kb + 4];
#pragma unroll
                for (int nt = 0; nt < 4; ++nt) {
                    mma_bf16(acc[mt][nt], a0h, a1h, a2h, a3h, bh0[nt], bh1[nt]);
                    mma_bf16(acc[mt][nt], a0h, a1h, a2h, a3h, bl0[nt], bl1[nt]);
                    mma_bf16(acc[mt][nt], a0l, a1l, a2l, a3l, bh0[nt], bh1[nt]);
                }
            }
        }
        __syncthreads();
    }
}

// ---------------------------------------------------------------------------
// Merged Q/K/V projection. grid (8, 32, 3): z selects weight/bias/output.
// z<2 -> split head-major out (scale folded into Q); z==2 -> V fp32 head-major.
// ---------------------------------------------------------------------------
__global__ __launch_bounds__(256, 2)
void proj_qkv(const unsigned* __restrict__ Xh, const unsigned* __restrict__ Xl,
              const unsigned* __restrict__ Wth, const unsigned* __restrict__ Wtl,
              const float* __restrict__ bq, const float* __restrict__ bk,
              const float* __restrict__ bv,
              unsigned* __restrict__ Qh, unsigned* __restrict__ Ql,
              unsigned* __restrict__ Kh, unsigned* __restrict__ Kl,
              float* __restrict__ Vout)
{
    extern __shared__ __align__(16) unsigned psm[];
    const int m0 = blockIdx.y * 128;
    const int n0 = blockIdx.x * 128;
    const int z  = blockIdx.z;

    float acc[4][4][4];
#pragma unroll
    for (int i = 0; i < 4; ++i)
#pragma unroll
        for (int j = 0; j < 4; ++j)
#pragma unroll
            for (int r = 0; r < 4; ++r) acc[i][j][r] = 0.f;

    proj_core(Xh + (size_t)m0 * 512, Xl + (size_t)m0 * 512,
              Wth + (size_t)z * WSZ + (size_t)n0 * 512,
              Wtl + (size_t)z * WSZ + (size_t)n0 * 512,
              psm, acc);

    const int lane = threadIdx.x & 31;
    const int wid  = threadIdx.x >> 5;
    const int wm   = wid & 1;
    const int wn   = wid >> 1;
    const int g    = lane >> 2;
    const int t    = lane & 3;

    const float* bias = (z == 0) ? bq : (z == 1) ? bk : bv;
    const float oscale = (z == 0) ? 0.03125f : 1.0f;
    unsigned* outh = (z == 0) ? Qh : Kh;
    unsigned* outl = (z == 0) ? Ql : Kl;

#pragma unroll
    for (int mt = 0; mt < 4; ++mt) {
#pragma unroll
        for (int nt = 0; nt < 4; ++nt) {
            const int row0 = m0 + wm * 64 + mt * 16 + g;
            const int col  = n0 + wn * 32 + nt * 8 + t * 2;
            const float b0v = __ldg(&bias[col]);
            const float b1v = __ldg(&bias[col + 1]);
#pragma unroll
            for (int half = 0; half < 2; ++half) {
                const int row = row0 + half * 8;
                float vx = (acc[mt][nt][half * 2 + 0] + b0v) * oscale;
                float vy = (acc[mt][nt][half * 2 + 1] + b1v) * oscale;
                const int b  = row >> 11;
                const int n  = row & (SEQ - 1);
                const int h  = col >> 6;
                if (z < 2) {
                    const int d2 = (col & (HD - 1)) >> 1;
                    unsigned hp, lp;
                    split2(vx, vy, hp, lp);
                    size_t idx = ((size_t)(b * HEADS + h) * SEQ + n) * 32 + d2;
                    outh[idx] = hp;
                    outl[idx] = lp;
                } else {
                    const int dd = col & (HD - 1);
                    float2 v; v.x = vx; v.y = vy;
                    *(float2*)(Vout + ((size_t)(b * HEADS + h) * SEQ + n) * HD + dd) = v;
                }
            }
        }
    }
}

// ---------------------------------------------------------------------------
// Final projection: ctx (pre-split, written by attention) x Wo + bo -> out.
// ---------------------------------------------------------------------------
__global__ __launch_bounds__(256, 2)
void proj_final(const unsigned* __restrict__ Ch, const unsigned* __restrict__ Cl,
                const unsigned* __restrict__ Wth, const unsigned* __restrict__ Wtl,
                const float* __restrict__ bias,
                float* __restrict__ out)
{
    extern __shared__ __align__(16) unsigned psm[];
    const int m0 = blockIdx.y * 128;
    const int n0 = blockIdx.x * 128;

    float acc[4][4][4];
#pragma unroll
    for (int i = 0; i < 4; ++i)
#pragma unroll
        for (int j = 0; j < 4; ++j)
#pragma unroll
            for (int r = 0; r < 4; ++r) acc[i][j][r] = 0.f;

    proj_core(Ch + (size_t)m0 * 512, Cl + (size_t)m0 * 512,
              Wth + (size_t)n0 * 512, Wtl + (size_t)n0 * 512,
              psm, acc);

    const int lane = threadIdx.x & 31;
    const int wid  = threadIdx.x >> 5;
    const int wm   = wid & 1;
    const int wn   = wid >> 1;
    const int g    = lane >> 2;
    const int t    = lane & 3;

#pragma unroll
    for (int mt = 0; mt < 4; ++mt) {
#pragma unroll
        for (int nt = 0; nt < 4; ++nt) {
            const int row0 = m0 + wm * 64 + mt * 16 + g;
            const int col  = n0 + wn * 32 + nt * 8 + t * 2;
            const float b0v = __ldg(&bias[col]);
            const float b1v = __ldg(&bias[col + 1]);
#pragma unroll
            for (int half = 0; half < 2; ++half) {
                const int row = row0 + half * 8;
                float2 v;
                v.x = acc[mt][nt][half * 2 + 0] + b0v;
                v.y = acc[mt][nt][half * 2 + 1] + b1v;
                *(float2*)(out + (size_t)row * EMB + col) = v;
            }
        }
    }
}

// ---------------------------------------------------------------------------
// Flash attention: pre-split inputs, cp.async double-buffered K/V tiles.
// Epilogue writes ctx PRE-SPLIT ([m][k2] row-major) for the final projection.
// ---------------------------------------------------------------------------
#define KVS 2304

__global__ __launch_bounds__(256)
void attn_mma_kernel(const unsigned* __restrict__ Qh, const unsigned* __restrict__ Ql,
                     const unsigned* __restrict__ Kh, const unsigned* __restrict__ Kl,
                     const unsigned* __restrict__ Vh, const unsigned* __restrict__ Vl,
                     unsigned* __restrict__ Ch, unsigned* __restrict__ Cl)
{
    extern __shared__ __align__(16) unsigned dynsm[];

    const int tid  = threadIdx.x;
    const int w    = tid >> 5;
    const int lane = tid & 31;
    const int g    = lane >> 2;
    const int t    = lane & 3;
    const int bh   = blockIdx.y;
    const int q0   = blockIdx.x * 128;

    const unsigned* Qhb = Qh + (size_t)bh * SEQ * 32;
    const unsigned* Qlb = Ql + (size_t)bh * SEQ * 32;
    const unsigned* Khb = Kh + (size_t)bh * SEQ * 32;
    const unsigned* Klb = Kl + (size_t)bh * SEQ * 32;
    const unsigned* Vhb = Vh + (size_t)bh * HD * (SEQ / 2);
    const unsigned* Vlb = Vl + (size_t)bh * HD * (SEQ / 2);

    unsigned qh[4][4], ql[4][4];
    const int r1 = q0 + w * 16 + g;
    const int r2 = r1 + 8;
#pragma unroll
    for (int ks = 0; ks < 4; ++ks) {
        int c0 = ks * 8 + t;
        qh[ks][0] = Qhb[(size_t)r1 * 32 + c0];
        qh[ks][1] = Qhb[(size_t)r2 * 32 + c0];
        qh[ks][2] = Qhb[(size_t)r1 * 32 + c0 + 4];
        qh[ks][3] = Qhb[(size_t)r2 * 32 + c0 + 4];
        ql[ks][0] = Qlb[(size_t)r1 * 32 + c0];
        ql[ks][1] = Qlb[(size_t)r2 * 32 + c0];
        ql[ks][2] = Qlb[(size_t)r1 * 32 + c0 + 4];
        ql[ks][3] = Qlb[(size_t)r2 * 32 + c0 + 4];
    }

    auto stage = [&](int buf, int kt) {
        unsigned* base = dynsm + buf * 4 * KVS;
#pragma unroll
        for (int u = 0; u < 4; ++u) {
            int id = tid + 256 * u;
            const unsigned* src = (id < 512) ? Khb : Klb;
            unsigned* dst = base + ((id < 512) ? 0 : KVS);
            int rem = id & 511;
            int key = rem >> 3, ch = (rem & 7) * 4;
            cp_async16(smem_u32addr(dst + key * 36 + ch),
                       src + (size_t)(kt + key) * 32 + ch);
        }
#pragma unroll
        for (int u = 0; u < 4; ++u) {
            int id = tid + 256 * u;
            const unsigned* src = (id < 512) ? Vhb : Vlb;
            unsigned* dst = base + 2 * KVS + ((id < 512) ? 0 : KVS);
            int rem = id & 511;
            int d = rem >> 3, ch = (rem & 7) * 4;
            cp_async16(smem_u32addr(dst + d * 36 + ch),
                       src + (size_t)d * (SEQ / 2) + (kt >> 1) + ch);
        }
        cp_commit();
    };

    float oacc[8][4];
#pragma unroll
    for (int j = 0; j < 8; ++j)
#pragma unroll
        for (int r = 0; r < 4; ++r) oacc[j][r] = 0.f;
    float m1 = -1e30f, m2 = -1e30f, l1s = 0.f, l2s = 0.f;

    stage(0, 0);

    const int NT = SEQ / 64;
    for (int it = 0; it < NT; ++it) {
        if (it + 1 < NT) {
            stage((it + 1) & 1, (it + 1) * 64);
            cp_wait<1>();
        } else {
            cp_wait<0>();
        }
        __syncthreads();

        const unsigned* kh = dynsm + (it & 1) * 4 * KVS;
        const unsigned* kl = kh + KVS;
        const unsigned* vh = kh + 2 * KVS;
        const unsigned* vl = kh + 3 * KVS;

        float sacc[8][4];
#pragma unroll
        for (int j = 0; j < 8; ++j)
#pragma unroll
            for (int r = 0; r < 4; ++r) sacc[j][r] = 0.f;

#pragma unroll
        for (int ks = 0; ks < 4; ++ks) {
#pragma unroll
            for (int j = 0; j < 8; ++j) {
                int ka = (8 * j + g) * 36 + ks * 8 + t;
                unsigned bh0 = kh[ka], bh1 = kh[ka + 4];
                unsigned bl0 = kl[ka], bl1 = kl[ka + 4];
                mma_bf16(sacc[j], qh[ks][0], qh[ks][1], qh[ks][2], qh[ks][3], bh0, bh1);
                mma_bf16(sacc[j], qh[ks][0], qh[ks][1], qh[ks][2], qh[ks][3], bl0, bl1);
                mma_bf16(sacc[j], ql[ks][0], ql[ks][1], ql[ks][2], ql[ks][3], bh0, bh1);
            }
        }

        float cm1 = -1e30f, cm2 = -1e30f;
#pragma unroll
        for (int j = 0; j < 8; ++j) {
            cm1 = fmaxf(cm1, fmaxf(sacc[j][0], sacc[j][1]));
            cm2 = fmaxf(cm2, fmaxf(sacc[j][2], sacc[j][3]));
        }
        cm1 = fmaxf(cm1, __shfl_xor_sync(0xffffffffu, cm1, 1));
        cm1 = fmaxf(cm1, __shfl_xor_sync(0xffffffffu, cm1, 2));
        cm2 = fmaxf(cm2, __shfl_xor_sync(0xffffffffu, cm2, 1));
        cm2 = fmaxf(cm2, __shfl_xor_sync(0xffffffffu, cm2, 2));
        const float mn1 = fmaxf(m1, cm1);
        const float mn2 = fmaxf(m2, cm2);
        const float f1 = __expf(m1 - mn1);
        const float f2 = __expf(m2 - mn2);
        m1 = mn1; m2 = mn2;

        float sp1 = 0.f, sp2 = 0.f;
#pragma unroll
        for (int j = 0; j < 8; ++j) {
            sacc[j][0] = __expf(sacc[j][0] - mn1);
            sacc[j][1] = __expf(sacc[j][1] - mn1);
            sacc[j][2] = __expf(sacc[j][2] - mn2);
            sacc[j][3] = __expf(sacc[j][3] - mn2);
            sp1 += sacc[j][0] + sacc[j][1];
            sp2 += sacc[j][2] + sacc[j][3];
        }
        sp1 += __shfl_xor_sync(0xffffffffu, sp1, 1);
        sp1 += __shfl_xor_sync(0xffffffffu, sp1, 2);
        sp2 += __shfl_xor_sync(0xffffffffu, sp2, 1);
        sp2 += __shfl_xor_sync(0xffffffffu, sp2, 2);
        l1s = l1s * f1 + sp1;
        l2s = l2s * f2 + sp2;

#pragma unroll
        for (int j = 0; j < 8; ++j) {
            oacc[j][0] *= f1; oacc[j][1] *= f1;
            oacc[j][2] *= f2; oacc[j][3] *= f2;
        }

#pragma unroll
        for (int s = 0; s < 4; ++s) {
            unsigned a0h, a0l, a1h, a1l, a2h, a2l, a3h, a3l;
            split2(sacc[2 * s][0],     sacc[2 * s][1],     a0h, a0l);
            split2(sacc[2 * s][2],     sacc[2 * s][3],     a1h, a1l);
            split2(sacc[2 * s + 1][0], sacc[2 * s + 1][1], a2h, a2l);
            split2(sacc[2 * s + 1][2], sacc[2 * s + 1][3], a3h, a3l);
#pragma unroll
            for (int j = 0; j < 8; ++j) {
                int va = (8 * j + g) * 36 + 8 * s + t;
                unsigned vh0 = vh[va], vh1 = vh[va + 4];
                unsigned vl0 = vl[va], vl1 = vl[va + 4];
                mma_bf16(oacc[j], a0h, a1h, a2h, a3h, vh0, vh1);
                mma_bf16(oacc[j], a0h, a1h, a2h, a3h, vl0, vl1);
                mma_bf16(oacc[j], a0l, a1l, a2l, a3l, vh0, vh1);
            }
        }
        __syncthreads();
    }

    // ---- Epilogue: normalize + write ctx pre-split [m][k2] ----
    const float inv1 = 1.f / l1s;
    const float inv2 = 1.f / l2s;
    const int b = bh >> 4;
    const int h = bh & 15;
#pragma unroll
    for (int j = 0; j < 8; ++j) {
        const int col = h * HD + 8 * j + 2 * t;
        unsigned hp, lp;
        split2(oacc[j][0] * inv1, oacc[j][1] * inv1, hp, lp);
        size_t i1 = (size_t)(b * SEQ + r1) * 512 + (col >> 1);
        Ch[i1] = hp;
        Cl[i1] = lp;
        split2(oacc[j][2] * inv2, oacc[j][3] * inv2, hp, lp);
        size_t i2 = (size_t)(b * SEQ + r2) * 512 + (col >> 1);
        Ch[i2] = hp;
        Cl[i2] = lp;
    }
}

// ---------------------------------------------------------------------------
// Launch
// ---------------------------------------------------------------------------
extern "C" void kernel_launch(void* const* d_in, const int* in_sizes, int n_in,
                              void* d_out, int out_size)
{
    const float* x  = (const float*)d_in[0];
    const float* Wq = (const float*)d_in[1];
    const float* bq = (const float*)d_in[2];
    const float* Wk = (const float*)d_in[3];
    const float* bk = (const float*)d_in[4];
    const float* Wv = (const float*)d_in[5];
    const float* bv = (const float*)d_in[6];
    const float* Wo = (const float*)d_in[7];
    const float* bo = (const float*)d_in[8];
    float* out = (float*)d_out;

    unsigned *Xh, *Xl, *Wth, *Wtl, *Qh, *Ql, *Kh, *Kl, *Vth, *Vtl;
    float *Vp;
    cudaGetSymbolAddress((void**)&Xh,  g_Xh);
    cudaGetSymbolAddress((void**)&Xl,  g_Xl);
    cudaGetSymbolAddress((void**)&Wth, g_Wth);
    cudaGetSymbolAddress((void**)&Wtl, g_Wtl);
    cudaGetSymbolAddress((void**)&Qh,  g_Qh);
    cudaGetSymbolAddress((void**)&Ql,  g_Ql);
    cudaGetSymbolAddress((void**)&Kh,  g_Kh);
    cudaGetSymbolAddress((void**)&Kl,  g_Kl);
    cudaGetSymbolAddress((void**)&Vth, g_Vth);
    cudaGetSymbolAddress((void**)&Vtl, g_Vtl);
    cudaGetSymbolAddress((void**)&Vp,  g_V);

    const int attn_smem = 2 * 4 * KVS * 4;   // 73728
    const int proj_smem = 2 * PBUF * 4;      // 81920
    static int configured = 0;
    if (!configured) {
        cudaFuncSetAttribute(attn_mma_kernel,
                             cudaFuncAttributeMaxDynamicSharedMemorySize, attn_smem);
        cudaFuncSetAttribute(proj_qkv,
                             cudaFuncAttributeMaxDynamicSharedMemorySize, proj_smem);
        cudaFuncSetAttribute(proj_final,
                             cudaFuncAttributeMaxDynamicSharedMemorySize, proj_smem);
        configured = 1;
    }

    // Prologue: split X + all weights (2 launches)
    split_rows<<<4096, 256>>>(x, Xh, Xl);
    split_all_w<<<dim3(16, 16, 4), 256>>>(Wq, Wk, Wv, Wo, Wth, Wtl);

    // Merged Q/K/V projection (one launch)
    proj_qkv<<<dim3(8, 32, 3), 256, proj_smem>>>(Xh, Xl, Wth, Wtl,
                                                 bq, bk, bv,
                                                 Qh, Ql, Kh, Kl, Vp);
    split_v_t<<<dim3(SEQ / 64, BH), 256>>>(Vp, Vth, Vtl);

    // Attention writes ctx pre-split into the (now free) X buffers
    dim3 agrid(SEQ / 128, BH);
    attn_mma_kernel<<<agrid, 256, attn_smem>>>(Qh, Ql, Kh, Kl, Vth, Vtl, Xh, Xl);

    // Final projection
    proj_final<<<dim3(8, 32), 256, proj_smem>>>(Xh, Xl,
                                                Wth + 3 * WSZ, Wtl + 3 * WSZ,
                                                bo, out);
}